// round 13
// baseline (speedup 1.0000x reference)
#include <cuda_runtime.h>
#include <cuda_fp16.h>
#include <math.h>
#include <stdint.h>

#define BB 8
#define NN 8192
#define EE 65536
#define FIN 64
#define HH 128
#define OUTD 256
#define MM (BB*NN)
#define ETOT (BB*EE)
#define HALF_M (MM/2)

// ---------------- scratch ----------------
__device__ __half g_xh0[MM*HH];
__device__ __half g_xh1[MM*HH];
__device__ __half g_aggh[MM*HH];
__device__ int    g_cnti[MM];
__device__ int    g_off[MM + 4];
__device__ int    g_slot[ETOT];
__device__ int    g_bsum[64];
__device__ int    g_csrc[ETOT];
__device__ float  g_cw[ETOT];
__device__ uint32_t g_wth[6*HH*HH/2 + HH*FIN/2];
__device__ float  g_pp[256*128];
__device__ float  g_pm[256*128];
__device__ float  g_pool[BB*2*HH];

// ---------------- fp16 helpers ----------------
__device__ __forceinline__ uint32_t pkh2(float x, float y) {
    __half2 h = __floats2half2_rn(x, y);
    return *reinterpret_cast<uint32_t*>(&h);
}
__device__ __forceinline__ float2 uph2(uint32_t v) {
    return __half22float2(*reinterpret_cast<const __half2*>(&v));
}
__device__ __forceinline__ void mma_f16(float* c, const uint32_t* a, uint32_t b0, uint32_t b1) {
    asm volatile("mma.sync.aligned.m16n8k16.row.col.f32.f16.f16.f32 "
                 "{%0,%1,%2,%3}, {%4,%5,%6,%7}, {%8,%9}, {%0,%1,%2,%3};"
                 : "+f"(c[0]), "+f"(c[1]), "+f"(c[2]), "+f"(c[3])
                 : "r"(a[0]), "r"(a[1]), "r"(a[2]), "r"(a[3]), "r"(b0), "r"(b1));
}

// ---------------- zero helper ----------------
__global__ void zero4_kernel(float4* __restrict__ p, int n4) {
    int i = blockIdx.x * blockDim.x + threadIdx.x;
    if (i < n4) p[i] = make_float4(0.f, 0.f, 0.f, 0.f);
}

// ---------------- CSR build ----------------
__global__ void count_kernel(const int* __restrict__ ei, const float* __restrict__ emask,
                             int* __restrict__ cnti, int* __restrict__ slot) {
    int e = blockIdx.x * blockDim.x + threadIdx.x;
    if (e >= ETOT) return;
    int b = e / EE, ee = e - b * EE;
    if (emask[e] != 0.f) {
        int tgt = ei[b * 2 * EE + EE + ee] + b * NN;
        slot[e] = atomicAdd(&cnti[tgt], 1);
    }
}

__global__ void psum_kernel(const int* __restrict__ cnt, int* __restrict__ bsum) {
    __shared__ int sh[1024];
    int t = threadIdx.x;
    sh[t] = cnt[blockIdx.x * 1024 + t];
    __syncthreads();
    for (int d = 512; d; d >>= 1) {
        if (t < d) sh[t] += sh[t + d];
        __syncthreads();
    }
    if (t == 0) bsum[blockIdx.x] = sh[0];
}

__global__ void emit_kernel(const int* __restrict__ cnt, const int* __restrict__ bsum,
                            int* __restrict__ off) {
    __shared__ int sh[1024];
    __shared__ int bpre, btot;
    int t = threadIdx.x, g = blockIdx.x * 1024 + t;
    int v = cnt[g];
    sh[t] = v;
    if (t == 0) {
        int p = 0, tot = 0;
        for (int i = 0; i < 64; i++) {
            int s = bsum[i];
            if (i < blockIdx.x) p += s;
            tot += s;
        }
        bpre = p;
        btot = tot;
    }
    __syncthreads();
    for (int d = 1; d < 1024; d <<= 1) {
        int u = (t >= d) ? sh[t - d] : 0;
        __syncthreads();
        sh[t] += u;
        __syncthreads();
    }
    off[g] = sh[t] - v + bpre;
    if (blockIdx.x == 63 && t == 1023) off[MM] = btot;
}

__global__ void fill_kernel(const int* __restrict__ ei, const float* __restrict__ emask,
                            const int* __restrict__ off, const int* __restrict__ slot,
                            int* __restrict__ csrc, float* __restrict__ cw) {
    int e = blockIdx.x * blockDim.x + threadIdx.x;
    if (e >= ETOT) return;
    int b = e / EE, ee = e - b * EE;
    float m = emask[e];
    if (m == 0.f) return;
    int src = ei[b * 2 * EE + ee] + b * NN;
    int tgt = ei[b * 2 * EE + EE + ee] + b * NN;
    int idx = off[tgt] + slot[e];
    csrc[idx] = src;
    cw[idx] = m;
}

// ---------------- weight transpose + fp16 pack ----------------
#define WT6 (6*HH*HH/2)
__global__ void wtrans_kernel(const float* __restrict__ sW, const float* __restrict__ nW,
                              const float* __restrict__ inW, uint32_t* __restrict__ wth) {
    int mat = blockIdx.x;
    if (mat < 6) {
        int l = mat >> 1, pass = mat & 1;
        const float* src = (pass ? nW : sW) + (size_t)l * HH * HH;
        uint32_t* dst = wth + (size_t)mat * (HH * HH / 2);
        for (int idx = threadIdx.x; idx < HH * HH / 2; idx += blockDim.x) {
            int n = idx >> 6, kk = idx & 63;
            dst[n * 64 + kk] = pkh2(src[(2 * kk) * HH + n], src[(2 * kk + 1) * HH + n]);
        }
    } else {
        uint32_t* dst = wth + WT6;
        for (int idx = threadIdx.x; idx < HH * FIN / 2; idx += blockDim.x) {
            int n = idx >> 5, kk = idx & 31;
            dst[n * 32 + kk] = pkh2(inW[(2 * kk) * HH + n], inW[(2 * kk + 1) * HH + n]);
        }
    }
}

// ---------------- CSR aggregation: warp per node (node-range chunk) ----------------
__global__ void agg_csr_kernel(const __half* __restrict__ xh, const int* __restrict__ off,
                               const int* __restrict__ csrc, const float* __restrict__ cw,
                               __half* __restrict__ outh, int nbase) {
    int warp = nbase + ((blockIdx.x * blockDim.x + threadIdx.x) >> 5);
    int lane = threadIdx.x & 31;
    const uint2* xv = (const uint2*)xh;
    int beg = off[warp], end = off[warp + 1];
    float ax = 0.f, ay = 0.f, az = 0.f, aw = 0.f, ws = 0.f;
    int e = beg;
    for (; e + 2 <= end; e += 2) {
        int s0 = csrc[e], s1 = csrc[e + 1];
        float w0 = cw[e], w1 = cw[e + 1];
        uint2 u0 = xv[(size_t)s0 * 32 + lane];
        uint2 u1 = xv[(size_t)s1 * 32 + lane];
        float2 p0 = uph2(u0.x), q0 = uph2(u0.y);
        float2 p1 = uph2(u1.x), q1 = uph2(u1.y);
        ax += p0.x * w0 + p1.x * w1;
        ay += p0.y * w0 + p1.y * w1;
        az += q0.x * w0 + q1.x * w1;
        aw += q0.y * w0 + q1.y * w1;
        ws += w0 + w1;
    }
    if (e < end) {
        int s0 = csrc[e];
        float w0 = cw[e];
        uint2 u0 = xv[(size_t)s0 * 32 + lane];
        float2 p0 = uph2(u0.x), q0 = uph2(u0.y);
        ax += p0.x * w0; ay += p0.y * w0; az += q0.x * w0; aw += q0.y * w0;
        ws += w0;
    }
    float inv = 1.0f / fmaxf(ws, 1.0f);
    uint2 o;
    o.x = pkh2(ax * inv, ay * inv);
    o.y = pkh2(az * inv, aw * inv);
    ((uint2*)outh)[(size_t)warp * 32 + lane] = o;
}

// ================= fp16 HMMA GEMMs: CTA 128x128, warps 4(M) x 2(N) =================
#define PSTR 20

// ---------------- input GEMM: xh0 = relu(feats @ inW + inb) ----------------
__global__ void __launch_bounds__(256, 2)
input_mma_kernel(const float* __restrict__ A, const uint32_t* __restrict__ Wh,
                 const float* __restrict__ bias, __half* __restrict__ xout) {
    __shared__ __align__(16) uint32_t As[128 * PSTR];
    __shared__ __align__(16) uint32_t Bs[128 * PSTR];

    const int tid = threadIdx.x;
    const int wid = tid >> 5, lane = tid & 31;
    const int wm = wid & 3, wn = wid >> 2;
    const int g = lane >> 2, t = lane & 3;
    const int m0 = blockIdx.x * 128;

    float acc[2][8][4];
#pragma unroll
    for (int mi = 0; mi < 2; mi++)
#pragma unroll
        for (int ni = 0; ni < 8; ni++)
#pragma unroll
            for (int c = 0; c < 4; c++) acc[mi][ni][c] = 0.f;

    const float* Asrc = A + (size_t)m0 * FIN;

#pragma unroll 1
    for (int ch = 0; ch < 2; ch++) {
        __syncthreads();
#pragma unroll
        for (int u = 0; u < 4; u++) {
            int idx = u * 256 + tid;
            int row = idx >> 3, c4 = idx & 7;
            float4 v = *(const float4*)&Asrc[(size_t)row * FIN + ch * 32 + c4 * 4];
            uint2 o = make_uint2(pkh2(v.x, v.y), pkh2(v.z, v.w));
            *(uint2*)&As[row * PSTR + c4 * 2] = o;
        }
#pragma unroll
        for (int u = 0; u < 2; u++) {
            int idx = u * 256 + tid;
            int row = idx >> 2, q = idx & 3;
            uint4 w = *(const uint4*)&Wh[(size_t)row * 32 + ch * 16 + q * 4];
            *(uint4*)&Bs[row * PSTR + q * 4] = w;
        }
        __syncthreads();
#pragma unroll
        for (int ks = 0; ks < 2; ks++) {
            uint32_t a[2][4], b[8][2];
#pragma unroll
            for (int mi = 0; mi < 2; mi++) {
                int base = (wm * 32 + mi * 16 + g) * PSTR + ks * 8 + t;
                a[mi][0] = As[base];
                a[mi][1] = As[base + 8 * PSTR];
                a[mi][2] = As[base + 4];
                a[mi][3] = As[base + 8 * PSTR + 4];
            }
#pragma unroll
            for (int ni = 0; ni < 8; ni++) {
                int nb = (wn * 64 + ni * 8 + g) * PSTR + ks * 8 + t;
                b[ni][0] = Bs[nb];
                b[ni][1] = Bs[nb + 4];
            }
#pragma unroll
            for (int mi = 0; mi < 2; mi++)
#pragma unroll
                for (int ni = 0; ni < 8; ni++)
                    mma_f16(acc[mi][ni], a[mi], b[ni][0], b[ni][1]);
        }
    }

    float cb[16];
#pragma unroll
    for (int ni = 0; ni < 8; ni++)
#pragma unroll
        for (int j = 0; j < 2; j++)
            cb[ni * 2 + j] = bias[wn * 64 + ni * 8 + 2 * t + j];
    uint32_t* xo32 = (uint32_t*)xout;
#pragma unroll
    for (int mi = 0; mi < 2; mi++)
#pragma unroll
        for (int h = 0; h < 2; h++) {
            int grow = m0 + wm * 32 + mi * 16 + g + 8 * h;
#pragma unroll
            for (int ni = 0; ni < 8; ni++) {
                float ox = fmaxf(acc[mi][ni][2 * h]     + cb[ni * 2],     0.f);
                float oy = fmaxf(acc[mi][ni][2 * h + 1] + cb[ni * 2 + 1], 0.f);
                xo32[(size_t)grow * 64 + wn * 32 + ni * 4 + t] = pkh2(ox, oy);
            }
        }
}

// ---------------- fused layer GEMM (double-buffered, node-range chunk) ----------------
__global__ void __launch_bounds__(256, 2)
layer_mma_kernel(const __half* __restrict__ xh, const __half* __restrict__ aggh,
                 const uint32_t* __restrict__ Wsh, const uint32_t* __restrict__ Wnh,
                 const float* __restrict__ bsb, const float* __restrict__ bnb,
                 const float* __restrict__ lng, const float* __restrict__ lnb,
                 const float* __restrict__ nmask, __half* __restrict__ xout, int nbase) {
    __shared__ __align__(16) uint32_t As[2][128 * PSTR];
    __shared__ __align__(16) uint32_t Bs[2][128 * PSTR];
    __shared__ float red[128][4];

    const int tid = threadIdx.x;
    const int wid = tid >> 5, lane = tid & 31;
    const int wm = wid & 3, wn = wid >> 2;
    const int g = lane >> 2, t = lane & 3;
    const int m0 = nbase + blockIdx.x * 128;
    const int srow = tid >> 2, sq = tid & 3;

    float acc[2][8][4];
#pragma unroll
    for (int mi = 0; mi < 2; mi++)
#pragma unroll
        for (int ni = 0; ni < 8; ni++)
#pragma unroll
            for (int c = 0; c < 4; c++) acc[mi][ni][c] = 0.f;

    const uint32_t* Apass[2] = {(const uint32_t*)xh + (size_t)m0 * 64,
                                (const uint32_t*)aggh + (size_t)m0 * 64};
    const uint32_t* Bpass[2] = {Wsh, Wnh};

    uint4 pva[2], pvb[2];
#pragma unroll
    for (int u = 0; u < 2; u++) {
        int row = srow + u * 64;
        pva[u] = *(const uint4*)&Apass[0][(size_t)row * 64 + sq * 4];
        pvb[u] = *(const uint4*)&Bpass[0][(size_t)row * 64 + sq * 4];
    }
#pragma unroll
    for (int u = 0; u < 2; u++) {
        int row = srow + u * 64;
        *(uint4*)&As[0][row * PSTR + sq * 4] = pva[u];
        *(uint4*)&Bs[0][row * PSTR + sq * 4] = pvb[u];
    }
#pragma unroll
    for (int u = 0; u < 2; u++) {
        int row = srow + u * 64;
        pva[u] = *(const uint4*)&Apass[0][(size_t)row * 64 + 16 + sq * 4];
        pvb[u] = *(const uint4*)&Bpass[0][(size_t)row * 64 + 16 + sq * 4];
    }
    __syncthreads();

#pragma unroll 1
    for (int ch = 0; ch < 8; ch++) {
        const int buf = ch & 1;
        if (ch < 7) {
#pragma unroll
            for (int u = 0; u < 2; u++) {
                int row = srow + u * 64;
                *(uint4*)&As[buf ^ 1][row * PSTR + sq * 4] = pva[u];
                *(uint4*)&Bs[buf ^ 1][row * PSTR + sq * 4] = pvb[u];
            }
        }
        if (ch < 6) {
            int nc = ch + 2;
            const uint32_t* A_ = Apass[nc >> 2];
            const uint32_t* B_ = Bpass[nc >> 2];
            int koff = (nc & 3) * 16;
#pragma unroll
            for (int u = 0; u < 2; u++) {
                int row = srow + u * 64;
                pva[u] = *(const uint4*)&A_[(size_t)row * 64 + koff + sq * 4];
                pvb[u] = *(const uint4*)&B_[(size_t)row * 64 + koff + sq * 4];
            }
        }
#pragma unroll
        for (int ks = 0; ks < 2; ks++) {
            uint32_t a[2][4], b[8][2];
#pragma unroll
            for (int mi = 0; mi < 2; mi++) {
                int base = (wm * 32 + mi * 16 + g) * PSTR + ks * 8 + t;
                a[mi][0] = As[buf][base];
                a[mi][1] = As[buf][base + 8 * PSTR];
                a[mi][2] = As[buf][base + 4];
                a[mi][3] = As[buf][base + 8 * PSTR + 4];
            }
#pragma unroll
            for (int ni = 0; ni < 8; ni++) {
                int nb = (wn * 64 + ni * 8 + g) * PSTR + ks * 8 + t;
                b[ni][0] = Bs[buf][nb];
                b[ni][1] = Bs[buf][nb + 4];
            }
#pragma unroll
            for (int mi = 0; mi < 2; mi++)
#pragma unroll
                for (int ni = 0; ni < 8; ni++)
                    mma_f16(acc[mi][ni], a[mi], b[ni][0], b[ni][1]);
        }
        __syncthreads();
    }

    // ---- epilogue: bias + relu + layernorm + mask -> fp16 ----
    float cb[16], cgv[16], cbv[16];
#pragma unroll
    for (int ni = 0; ni < 8; ni++)
#pragma unroll
        for (int j = 0; j < 2; j++) {
            int c = wn * 64 + ni * 8 + 2 * t + j;
            cb[ni * 2 + j]  = bsb[c] + bnb[c];
            cgv[ni * 2 + j] = lng[c];
            cbv[ni * 2 + j] = lnb[c];
        }
#pragma unroll
    for (int mi = 0; mi < 2; mi++)
#pragma unroll
        for (int h = 0; h < 2; h++) {
            float s1 = 0.f, s2 = 0.f;
#pragma unroll
            for (int ni = 0; ni < 8; ni++)
#pragma unroll
                for (int j = 0; j < 2; j++) {
                    float v = fmaxf(acc[mi][ni][2 * h + j] + cb[ni * 2 + j], 0.f);
                    acc[mi][ni][2 * h + j] = v;
                    s1 += v;
                    s2 += v * v;
                }
            s1 += __shfl_xor_sync(0xffffffffu, s1, 1);
            s1 += __shfl_xor_sync(0xffffffffu, s1, 2);
            s2 += __shfl_xor_sync(0xffffffffu, s2, 1);
            s2 += __shfl_xor_sync(0xffffffffu, s2, 2);
            if (t == 0) {
                int row = wm * 32 + mi * 16 + g + 8 * h;
                red[row][wn * 2]     = s1;
                red[row][wn * 2 + 1] = s2;
            }
        }
    __syncthreads();
    uint32_t* xo32 = (uint32_t*)xout;
#pragma unroll
    for (int mi = 0; mi < 2; mi++)
#pragma unroll
        for (int h = 0; h < 2; h++) {
            int row = wm * 32 + mi * 16 + g + 8 * h;
            float s1 = red[row][0] + red[row][2];
            float s2 = red[row][1] + red[row][3];
            float mean = s1 * (1.0f / 128.0f);
            float var = fmaxf(s2 * (1.0f / 128.0f) - mean * mean, 0.f);
            float inv = rsqrtf(var + 1e-5f);
            int grow = m0 + row;
            float mk = nmask[grow];
#pragma unroll
            for (int ni = 0; ni < 8; ni++) {
                float ox = ((acc[mi][ni][2 * h]     - mean) * inv * cgv[ni * 2]     + cbv[ni * 2])     * mk;
                float oy = ((acc[mi][ni][2 * h + 1] - mean) * inv * cgv[ni * 2 + 1] + cbv[ni * 2 + 1]) * mk;
                xo32[(size_t)grow * 64 + wn * 32 + ni * 4 + t] = pkh2(ox, oy);
            }
        }
}

// ---------------- pool: two-stage, coalesced uint2 reads ----------------
__global__ void pool_partial_kernel(const __half* __restrict__ x, const float* __restrict__ nmask,
                                    float* __restrict__ pp, float* __restrict__ pm) {
    int blk = blockIdx.x;
    int b = blk >> 5, nc = blk & 31;
    int t = threadIdx.x;
    int g = t >> 5, l = t & 31;
    const uint2* xv = (const uint2*)x;
    float s0 = 0.f, s1 = 0.f, s2 = 0.f, s3 = 0.f;
    float m0 = -INFINITY, m1 = -INFINITY, m2 = -INFINITY, m3 = -INFINITY;
#pragma unroll 4
    for (int i = 0; i < 32; i++) {
        int n = nc * 256 + g * 32 + i;
        float mk = nmask[b * NN + n];
        uint2 u = xv[((size_t)(b * NN + n)) * 32 + l];
        float2 p = uph2(u.x), q = uph2(u.y);
        s0 += p.x * mk; s1 += p.y * mk; s2 += q.x * mk; s3 += q.y * mk;
        if (mk > 0.f) {
            m0 = fmaxf(m0, p.x * mk); m1 = fmaxf(m1, p.y * mk);
            m2 = fmaxf(m2, q.x * mk); m3 = fmaxf(m3, q.y * mk);
        }
    }
    __shared__ float sh[8][32][4];
    sh[g][l][0] = s0; sh[g][l][1] = s1; sh[g][l][2] = s2; sh[g][l][3] = s3;
    __syncthreads();
    if (g < 4) {
        int c = g * 32 + l;
        int ll = c >> 2, j = c & 3;
        float acc = 0.f;
#pragma unroll
        for (int k = 0; k < 8; k++) acc += sh[k][ll][j];
        pp[blk * 128 + c] = acc;
    }
    __syncthreads();
    sh[g][l][0] = m0; sh[g][l][1] = m1; sh[g][l][2] = m2; sh[g][l][3] = m3;
    __syncthreads();
    if (g < 4) {
        int c = g * 32 + l;
        int ll = c >> 2, j = c & 3;
        float acc = -INFINITY;
#pragma unroll
        for (int k = 0; k < 8; k++) acc = fmaxf(acc, sh[k][ll][j]);
        pm[blk * 128 + c] = acc;
    }
}

__global__ void pool_final_kernel(const float* __restrict__ pp, const float* __restrict__ pm,
                                  const float* __restrict__ nmask, float* __restrict__ pool) {
    int b = blockIdx.x, c = threadIdx.x;
    float s = 0.f, mx = -INFINITY;
#pragma unroll
    for (int k = 0; k < 32; k++) {
        s += pp[(b * 32 + k) * 128 + c];
        mx = fmaxf(mx, pm[(b * 32 + k) * 128 + c]);
    }
    float cv = 0.f;
    for (int n = c; n < NN; n += 128) cv += nmask[b * NN + n];
    __shared__ float sc[128];
    sc[c] = cv;
    __syncthreads();
    for (int d = 64; d; d >>= 1) {
        if (c < d) sc[c] += sc[c + d];
        __syncthreads();
    }
    float cnt = fmaxf(sc[0], 1.f);
    pool[b * 256 + c] = s / cnt;
    pool[b * 256 + 128 + c] = mx;
}

// ---------------- output MLP ----------------
__global__ void mlp_kernel(const float* __restrict__ pool, const float* __restrict__ W1,
                           const float* __restrict__ b1, const float* __restrict__ W2,
                           const float* __restrict__ b2, float* __restrict__ out) {
    __shared__ float gs[256], hs[128];
    int b = blockIdx.x, tid = threadIdx.x;
    gs[tid] = pool[b * 256 + tid];
    __syncthreads();
    if (tid < 128) {
        float a = b1[tid];
        for (int k = 0; k < 256; k++) a = fmaf(gs[k], W1[k * 128 + tid], a);
        hs[tid] = fmaxf(a, 0.f);
    }
    __syncthreads();
    float a = b2[tid];
    for (int k = 0; k < 128; k++) a = fmaf(hs[k], W2[k * 256 + tid], a);
    out[b * 256 + tid] = a;
}

// ---------------- launch ----------------
extern "C" void kernel_launch(void* const* d_in, const int* in_sizes, int n_in,
                              void* d_out, int out_size) {
    const float* feats = (const float*)d_in[0];
    const int*   ei    = (const int*)d_in[1];
    const float* nmask = (const float*)d_in[2];
    const float* emask = (const float*)d_in[3];
    const float* inW   = (const float*)d_in[4];
    const float* inb   = (const float*)d_in[5];
    const float* sW    = (const float*)d_in[6];
    const float* sb    = (const float*)d_in[7];
    const float* nW    = (const float*)d_in[8];
    const float* nb    = (const float*)d_in[9];
    const float* lng   = (const float*)d_in[10];
    const float* lnb   = (const float*)d_in[11];
    const float* w1    = (const float*)d_in[12];
    const float* b1    = (const float*)d_in[13];
    const float* w2    = (const float*)d_in[14];
    const float* b2    = (const float*)d_in[15];

    __half *xh0, *xh1, *aggh;
    float *pool, *cw, *pp, *pm;
    uint32_t* wth;
    int *cnti, *off, *slot, *csrc, *bsum;
    cudaGetSymbolAddress((void**)&xh0,  g_xh0);
    cudaGetSymbolAddress((void**)&xh1,  g_xh1);
    cudaGetSymbolAddress((void**)&aggh, g_aggh);
    cudaGetSymbolAddress((void**)&cnti, g_cnti);
    cudaGetSymbolAddress((void**)&off,  g_off);
    cudaGetSymbolAddress((void**)&slot, g_slot);
    cudaGetSymbolAddress((void**)&bsum, g_bsum);
    cudaGetSymbolAddress((void**)&csrc, g_csrc);
    cudaGetSymbolAddress((void**)&cw,   g_cw);
    cudaGetSymbolAddress((void**)&wth,  g_wth);
    cudaGetSymbolAddress((void**)&pp,   g_pp);
    cudaGetSymbolAddress((void**)&pm,   g_pm);
    cudaGetSymbolAddress((void**)&pool, g_pool);

    // side stream + events (created once, on the uncaptured correctness call)
    static cudaStream_t s1 = nullptr;
    static cudaEvent_t evFork = nullptr, evJoin = nullptr;
    static cudaEvent_t evX[3], evA[3];
    if (s1 == nullptr) {
        cudaStreamCreateWithFlags(&s1, cudaStreamNonBlocking);
        cudaEventCreateWithFlags(&evFork, cudaEventDisableTiming);
        cudaEventCreateWithFlags(&evJoin, cudaEventDisableTiming);
        for (int i = 0; i < 3; i++) {
            cudaEventCreateWithFlags(&evX[i], cudaEventDisableTiming);
            cudaEventCreateWithFlags(&evA[i], cudaEventDisableTiming);
        }
    }

    // fork: side stream runs the input-projection chain
    cudaEventRecord(evFork, 0);
    cudaStreamWaitEvent(s1, evFork, 0);

    // main stream: CSR build chain
    zero4_kernel<<<(MM / 4 + 255) / 256, 256>>>((float4*)cnti, MM / 4);
    count_kernel<<<(ETOT + 255) / 256, 256>>>(ei, emask, cnti, slot);
    psum_kernel<<<64, 1024>>>(cnti, bsum);
    emit_kernel<<<64, 1024>>>(cnti, bsum, off);
    fill_kernel<<<(ETOT + 255) / 256, 256>>>(ei, emask, off, slot, csrc, cw);

    // side stream: weight pack + input GEMM
    wtrans_kernel<<<7, 256, 0, s1>>>(sW, nW, inW, wth);
    input_mma_kernel<<<MM / 128, 256, 0, s1>>>(feats, wth + WT6, inb, xh0);
    cudaEventRecord(evJoin, s1);
    cudaStreamWaitEvent(0, evJoin, 0);

    // layers: node-halved, agg(c1) on side stream overlaps layer(c0) on main
    const int AGG_GRID = HALF_M * 32 / 256;    // 4096
    const int LYR_GRID = HALF_M / 128;         // 256
    __half* xin = xh0;
    __half* xo  = xh1;
    for (int l = 0; l < 3; l++) {
        const uint32_t* Ws = wth + (size_t)(l * 2) * (HH * HH / 2);
        const uint32_t* Wn = wth + (size_t)(l * 2 + 1) * (HH * HH / 2);
        // xin is complete on main stream here; hand it to the side stream
        cudaEventRecord(evX[l], 0);
        cudaStreamWaitEvent(s1, evX[l], 0);
        // chunk 0 gather on main, chunk 1 gather on side
        agg_csr_kernel<<<AGG_GRID, 256>>>(xin, off, csrc, cw, aggh, 0);
        agg_csr_kernel<<<AGG_GRID, 256, 0, s1>>>(xin, off, csrc, cw, aggh, HALF_M);
        cudaEventRecord(evA[l], s1);
        // layer chunk 0 (overlaps agg chunk 1)
        layer_mma_kernel<<<LYR_GRID, 256>>>(xin, aggh, Ws, Wn,
                                            sb + l * HH, nb + l * HH,
                                            lng + l * HH, lnb + l * HH,
                                            nmask, xo, 0);
        // layer chunk 1 (needs agg chunk 1)
        cudaStreamWaitEvent(0, evA[l], 0);
        layer_mma_kernel<<<LYR_GRID, 256>>>(xin, aggh, Ws, Wn,
                                            sb + l * HH, nb + l * HH,
                                            lng + l * HH, lnb + l * HH,
                                            nmask, xo, HALF_M);
        __half* t = xin; xin = xo; xo = t;
    }

    pool_partial_kernel<<<256, 256>>>(xin, nmask, pp, pm);
    pool_final_kernel<<<BB, 128>>>(pp, pm, nmask, pool);
    mlp_kernel<<<BB, 256>>>(pool, w1, b1, w2, b2, (float*)d_out);
}

// round 15
// speedup vs baseline: 1.0244x; 1.0244x over previous
#include <cuda_runtime.h>
#include <cuda_fp16.h>
#include <math.h>
#include <stdint.h>

#define BB 8
#define NN 8192
#define EE 65536
#define FIN 64
#define HH 128
#define OUTD 256
#define MM (BB*NN)
#define ETOT (BB*EE)

// ---------------- scratch ----------------
__device__ __half g_xh0[MM*HH];
__device__ __half g_xh1[MM*HH];
__device__ __half g_aggh[MM*HH];
__device__ int    g_cnti[MM];
__device__ int    g_off[MM + 4];
__device__ int    g_slot[ETOT];
__device__ int    g_tstat[64];
__device__ int    g_csrc[ETOT];
__device__ float  g_cw[ETOT];
__device__ uint32_t g_wth[6*HH*HH/2 + HH*FIN/2];
__device__ float  g_pp[256*128];
__device__ float  g_pm[256*128];

// ---------------- fp16 helpers ----------------
__device__ __forceinline__ uint32_t pkh2(float x, float y) {
    __half2 h = __floats2half2_rn(x, y);
    return *reinterpret_cast<uint32_t*>(&h);
}
__device__ __forceinline__ float2 uph2(uint32_t v) {
    return __half22float2(*reinterpret_cast<const __half2*>(&v));
}
__device__ __forceinline__ void mma_f16(float* c, const uint32_t* a, uint32_t b0, uint32_t b1) {
    asm volatile("mma.sync.aligned.m16n8k16.row.col.f32.f16.f16.f32 "
                 "{%0,%1,%2,%3}, {%4,%5,%6,%7}, {%8,%9}, {%0,%1,%2,%3};"
                 : "+f"(c[0]), "+f"(c[1]), "+f"(c[2]), "+f"(c[3])
                 : "r"(a[0]), "r"(a[1]), "r"(a[2]), "r"(a[3]), "r"(b0), "r"(b1));
}

// ---------------- CSR build ----------------
__global__ void count_kernel(const int* __restrict__ ei, const float* __restrict__ emask,
                             int* __restrict__ cnti, int* __restrict__ slot) {
    // reset scan status array for this replay (count always precedes scan)
    if (blockIdx.x == 0 && threadIdx.x < 64) g_tstat[threadIdx.x] = 0;
    int e = blockIdx.x * blockDim.x + threadIdx.x;
    if (e >= ETOT) return;
    int b = e / EE, ee = e - b * EE;
    if (emask[e] != 0.f) {
        int tgt = ei[b * 2 * EE + EE + ee] + b * NN;
        slot[e] = atomicAdd(&cnti[tgt], 1);
    }
}

// single-pass scan with decoupled lookback (64 tiles of 1024)
__global__ void scan_kernel(const int* __restrict__ cnt, int* __restrict__ off) {
    __shared__ int sh[1024];
    __shared__ int exc;
    volatile int* tstat = g_tstat;
    const int b = blockIdx.x, t = threadIdx.x;
    const int g = b * 1024 + t;
    int v = cnt[g];
    sh[t] = v;
    __syncthreads();
    for (int d = 1; d < 1024; d <<= 1) {
        int u = (t >= d) ? sh[t - d] : 0;
        __syncthreads();
        sh[t] += u;
        __syncthreads();
    }
    const int total = sh[1023];
    if (t == 0) {
        if (b == 0) {
            __threadfence();
            tstat[0] = (2 << 28) | total;
            exc = 0;
        } else {
            __threadfence();
            tstat[b] = (1 << 28) | total;   // publish aggregate
            int ex = 0;
            int i = b - 1;
            while (i >= 0) {
                int s;
                do { s = tstat[i]; } while ((s >> 28) == 0);
                ex += s & 0x0FFFFFFF;
                if ((s >> 28) == 2) break;
                i--;
            }
            exc = ex;
            __threadfence();
            tstat[b] = (2 << 28) | (ex + total);
        }
    }
    __syncthreads();
    off[g] = sh[t] - v + exc;
    if (b == 63 && t == 1023) off[MM] = exc + total;
}

__global__ void fill_kernel(const int* __restrict__ ei, const float* __restrict__ emask,
                            const int* __restrict__ off, const int* __restrict__ slot,
                            int* __restrict__ csrc, float* __restrict__ cw) {
    int e = blockIdx.x * blockDim.x + threadIdx.x;
    if (e >= ETOT) return;
    int b = e / EE, ee = e - b * EE;
    float m = emask[e];
    if (m == 0.f) return;
    int src = ei[b * 2 * EE + ee] + b * NN;
    int tgt = ei[b * 2 * EE + EE + ee] + b * NN;
    int idx = off[tgt] + slot[e];
    csrc[idx] = src;
    cw[idx] = m;
}

// ---------------- weight transpose + fp16 pack ----------------
#define WT6 (6*HH*HH/2)
__global__ void wtrans_kernel(const float* __restrict__ sW, const float* __restrict__ nW,
                              const float* __restrict__ inW, uint32_t* __restrict__ wth) {
    int mat = blockIdx.x;
    if (mat < 6) {
        int l = mat >> 1, pass = mat & 1;
        const float* src = (pass ? nW : sW) + (size_t)l * HH * HH;
        uint32_t* dst = wth + (size_t)mat * (HH * HH / 2);
        for (int idx = threadIdx.x; idx < HH * HH / 2; idx += blockDim.x) {
            int n = idx >> 6, kk = idx & 63;
            dst[n * 64 + kk] = pkh2(src[(2 * kk) * HH + n], src[(2 * kk + 1) * HH + n]);
        }
    } else {
        uint32_t* dst = wth + WT6;
        for (int idx = threadIdx.x; idx < HH * FIN / 2; idx += blockDim.x) {
            int n = idx >> 5, kk = idx & 31;
            dst[n * 32 + kk] = pkh2(inW[(2 * kk) * HH + n], inW[(2 * kk + 1) * HH + n]);
        }
    }
}

// ---------------- CSR aggregation: warp per node, fp16 gather ----------------
__global__ void agg_csr_kernel(const __half* __restrict__ xh, const int* __restrict__ off,
                               const int* __restrict__ csrc, const float* __restrict__ cw,
                               __half* __restrict__ outh) {
    int warp = (blockIdx.x * blockDim.x + threadIdx.x) >> 5;
    int lane = threadIdx.x & 31;
    if (warp >= MM) return;
    const uint2* xv = (const uint2*)xh;
    int beg = off[warp], end = off[warp + 1];
    float ax = 0.f, ay = 0.f, az = 0.f, aw = 0.f, ws = 0.f;
    int e = beg;
    for (; e + 2 <= end; e += 2) {
        int s0 = csrc[e], s1 = csrc[e + 1];
        float w0 = cw[e], w1 = cw[e + 1];
        uint2 u0 = xv[(size_t)s0 * 32 + lane];
        uint2 u1 = xv[(size_t)s1 * 32 + lane];
        float2 p0 = uph2(u0.x), q0 = uph2(u0.y);
        float2 p1 = uph2(u1.x), q1 = uph2(u1.y);
        ax += p0.x * w0 + p1.x * w1;
        ay += p0.y * w0 + p1.y * w1;
        az += q0.x * w0 + q1.x * w1;
        aw += q0.y * w0 + q1.y * w1;
        ws += w0 + w1;
    }
    if (e < end) {
        int s0 = csrc[e];
        float w0 = cw[e];
        uint2 u0 = xv[(size_t)s0 * 32 + lane];
        float2 p0 = uph2(u0.x), q0 = uph2(u0.y);
        ax += p0.x * w0; ay += p0.y * w0; az += q0.x * w0; aw += q0.y * w0;
        ws += w0;
    }
    float inv = 1.0f / fmaxf(ws, 1.0f);
    uint2 o;
    o.x = pkh2(ax * inv, ay * inv);
    o.y = pkh2(az * inv, aw * inv);
    ((uint2*)outh)[(size_t)warp * 32 + lane] = o;
}

// ================= fp16 HMMA GEMMs: CTA 128x128, warps 4(M) x 2(N) =================
#define PSTR 20

// ---------------- input GEMM: xh0 = relu(feats @ inW + inb) ----------------
__global__ void __launch_bounds__(256, 2)
input_mma_kernel(const float* __restrict__ A, const uint32_t* __restrict__ Wh,
                 const float* __restrict__ bias, __half* __restrict__ xout) {
    __shared__ __align__(16) uint32_t As[128 * PSTR];
    __shared__ __align__(16) uint32_t Bs[128 * PSTR];

    const int tid = threadIdx.x;
    const int wid = tid >> 5, lane = tid & 31;
    const int wm = wid & 3, wn = wid >> 2;
    const int g = lane >> 2, t = lane & 3;
    const int m0 = blockIdx.x * 128;

    float acc[2][8][4];
#pragma unroll
    for (int mi = 0; mi < 2; mi++)
#pragma unroll
        for (int ni = 0; ni < 8; ni++)
#pragma unroll
            for (int c = 0; c < 4; c++) acc[mi][ni][c] = 0.f;

    const float* Asrc = A + (size_t)m0 * FIN;

#pragma unroll 1
    for (int ch = 0; ch < 2; ch++) {
        __syncthreads();
#pragma unroll
        for (int u = 0; u < 4; u++) {
            int idx = u * 256 + tid;
            int row = idx >> 3, c4 = idx & 7;
            float4 v = *(const float4*)&Asrc[(size_t)row * FIN + ch * 32 + c4 * 4];
            uint2 o = make_uint2(pkh2(v.x, v.y), pkh2(v.z, v.w));
            *(uint2*)&As[row * PSTR + c4 * 2] = o;
        }
#pragma unroll
        for (int u = 0; u < 2; u++) {
            int idx = u * 256 + tid;
            int row = idx >> 2, q = idx & 3;
            uint4 w = *(const uint4*)&Wh[(size_t)row * 32 + ch * 16 + q * 4];
            *(uint4*)&Bs[row * PSTR + q * 4] = w;
        }
        __syncthreads();
#pragma unroll
        for (int ks = 0; ks < 2; ks++) {
            uint32_t a[2][4], b[8][2];
#pragma unroll
            for (int mi = 0; mi < 2; mi++) {
                int base = (wm * 32 + mi * 16 + g) * PSTR + ks * 8 + t;
                a[mi][0] = As[base];
                a[mi][1] = As[base + 8 * PSTR];
                a[mi][2] = As[base + 4];
                a[mi][3] = As[base + 8 * PSTR + 4];
            }
#pragma unroll
            for (int ni = 0; ni < 8; ni++) {
                int nb = (wn * 64 + ni * 8 + g) * PSTR + ks * 8 + t;
                b[ni][0] = Bs[nb];
                b[ni][1] = Bs[nb + 4];
            }
#pragma unroll
            for (int mi = 0; mi < 2; mi++)
#pragma unroll
                for (int ni = 0; ni < 8; ni++)
                    mma_f16(acc[mi][ni], a[mi], b[ni][0], b[ni][1]);
        }
    }

    float cb[16];
#pragma unroll
    for (int ni = 0; ni < 8; ni++)
#pragma unroll
        for (int j = 0; j < 2; j++)
            cb[ni * 2 + j] = bias[wn * 64 + ni * 8 + 2 * t + j];
    uint32_t* xo32 = (uint32_t*)xout;
#pragma unroll
    for (int mi = 0; mi < 2; mi++)
#pragma unroll
        for (int h = 0; h < 2; h++) {
            int grow = m0 + wm * 32 + mi * 16 + g + 8 * h;
#pragma unroll
            for (int ni = 0; ni < 8; ni++) {
                float ox = fmaxf(acc[mi][ni][2 * h]     + cb[ni * 2],     0.f);
                float oy = fmaxf(acc[mi][ni][2 * h + 1] + cb[ni * 2 + 1], 0.f);
                xo32[(size_t)grow * 64 + wn * 32 + ni * 4 + t] = pkh2(ox, oy);
            }
        }
}

// ---------------- fused layer GEMM (double-buffered smem, 1 sync/chunk) ----------------
__global__ void __launch_bounds__(256, 2)
layer_mma_kernel(const __half* __restrict__ xh, const __half* __restrict__ aggh,
                 const uint32_t* __restrict__ Wsh, const uint32_t* __restrict__ Wnh,
                 const float* __restrict__ bsb, const float* __restrict__ bnb,
                 const float* __restrict__ lng, const float* __restrict__ lnb,
                 const float* __restrict__ nmask, __half* __restrict__ xout) {
    __shared__ __align__(16) uint32_t As[2][128 * PSTR];
    __shared__ __align__(16) uint32_t Bs[2][128 * PSTR];
    __shared__ float red[128][4];

    const int tid = threadIdx.x;
    const int wid = tid >> 5, lane = tid & 31;
    const int wm = wid & 3, wn = wid >> 2;
    const int g = lane >> 2, t = lane & 3;
    const int m0 = blockIdx.x * 128;
    const int srow = tid >> 2, sq = tid & 3;

    float acc[2][8][4];
#pragma unroll
    for (int mi = 0; mi < 2; mi++)
#pragma unroll
        for (int ni = 0; ni < 8; ni++)
#pragma unroll
            for (int c = 0; c < 4; c++) acc[mi][ni][c] = 0.f;

    const uint32_t* Apass[2] = {(const uint32_t*)xh + (size_t)m0 * 64,
                                (const uint32_t*)aggh + (size_t)m0 * 64};
    const uint32_t* Bpass[2] = {Wsh, Wnh};

    uint4 pva[2], pvb[2];
#pragma unroll
    for (int u = 0; u < 2; u++) {
        int row = srow + u * 64;
        pva[u] = *(const uint4*)&Apass[0][(size_t)row * 64 + sq * 4];
        pvb[u] = *(const uint4*)&Bpass[0][(size_t)row * 64 + sq * 4];
    }
#pragma unroll
    for (int u = 0; u < 2; u++) {
        int row = srow + u * 64;
        *(uint4*)&As[0][row * PSTR + sq * 4] = pva[u];
        *(uint4*)&Bs[0][row * PSTR + sq * 4] = pvb[u];
    }
#pragma unroll
    for (int u = 0; u < 2; u++) {
        int row = srow + u * 64;
        pva[u] = *(const uint4*)&Apass[0][(size_t)row * 64 + 16 + sq * 4];
        pvb[u] = *(const uint4*)&Bpass[0][(size_t)row * 64 + 16 + sq * 4];
    }
    __syncthreads();

#pragma unroll 1
    for (int ch = 0; ch < 8; ch++) {
        const int buf = ch & 1;
        if (ch < 7) {
#pragma unroll
            for (int u = 0; u < 2; u++) {
                int row = srow + u * 64;
                *(uint4*)&As[buf ^ 1][row * PSTR + sq * 4] = pva[u];
                *(uint4*)&Bs[buf ^ 1][row * PSTR + sq * 4] = pvb[u];
            }
        }
        if (ch < 6) {
            int nc = ch + 2;
            const uint32_t* A_ = Apass[nc >> 2];
            const uint32_t* B_ = Bpass[nc >> 2];
            int koff = (nc & 3) * 16;
#pragma unroll
            for (int u = 0; u < 2; u++) {
                int row = srow + u * 64;
                pva[u] = *(const uint4*)&A_[(size_t)row * 64 + koff + sq * 4];
                pvb[u] = *(const uint4*)&B_[(size_t)row * 64 + koff + sq * 4];
            }
        }
#pragma unroll
        for (int ks = 0; ks < 2; ks++) {
            uint32_t a[2][4], b[8][2];
#pragma unroll
            for (int mi = 0; mi < 2; mi++) {
                int base = (wm * 32 + mi * 16 + g) * PSTR + ks * 8 + t;
                a[mi][0] = As[buf][base];
                a[mi][1] = As[buf][base + 8 * PSTR];
                a[mi][2] = As[buf][base + 4];
                a[mi][3] = As[buf][base + 8 * PSTR + 4];
            }
#pragma unroll
            for (int ni = 0; ni < 8; ni++) {
                int nb = (wn * 64 + ni * 8 + g) * PSTR + ks * 8 + t;
                b[ni][0] = Bs[buf][nb];
                b[ni][1] = Bs[buf][nb + 4];
            }
#pragma unroll
            for (int mi = 0; mi < 2; mi++)
#pragma unroll
                for (int ni = 0; ni < 8; ni++)
                    mma_f16(acc[mi][ni], a[mi], b[ni][0], b[ni][1]);
        }
        __syncthreads();
    }

    // ---- epilogue: bias + relu + layernorm + mask -> fp16 ----
    float cb[16], cgv[16], cbv[16];
#pragma unroll
    for (int ni = 0; ni < 8; ni++)
#pragma unroll
        for (int j = 0; j < 2; j++) {
            int c = wn * 64 + ni * 8 + 2 * t + j;
            cb[ni * 2 + j]  = bsb[c] + bnb[c];
            cgv[ni * 2 + j] = lng[c];
            cbv[ni * 2 + j] = lnb[c];
        }
#pragma unroll
    for (int mi = 0; mi < 2; mi++)
#pragma unroll
        for (int h = 0; h < 2; h++) {
            float s1 = 0.f, s2 = 0.f;
#pragma unroll
            for (int ni = 0; ni < 8; ni++)
#pragma unroll
                for (int j = 0; j < 2; j++) {
                    float v = fmaxf(acc[mi][ni][2 * h + j] + cb[ni * 2 + j], 0.f);
                    acc[mi][ni][2 * h + j] = v;
                    s1 += v;
                    s2 += v * v;
                }
            s1 += __shfl_xor_sync(0xffffffffu, s1, 1);
            s1 += __shfl_xor_sync(0xffffffffu, s1, 2);
            s2 += __shfl_xor_sync(0xffffffffu, s2, 1);
            s2 += __shfl_xor_sync(0xffffffffu, s2, 2);
            if (t == 0) {
                int row = wm * 32 + mi * 16 + g + 8 * h;
                red[row][wn * 2]     = s1;
                red[row][wn * 2 + 1] = s2;
            }
        }
    __syncthreads();
    uint32_t* xo32 = (uint32_t*)xout;
#pragma unroll
    for (int mi = 0; mi < 2; mi++)
#pragma unroll
        for (int h = 0; h < 2; h++) {
            int row = wm * 32 + mi * 16 + g + 8 * h;
            float s1 = red[row][0] + red[row][2];
            float s2 = red[row][1] + red[row][3];
            float mean = s1 * (1.0f / 128.0f);
            float var = fmaxf(s2 * (1.0f / 128.0f) - mean * mean, 0.f);
            float inv = rsqrtf(var + 1e-5f);
            int grow = m0 + row;
            float mk = nmask[grow];
#pragma unroll
            for (int ni = 0; ni < 8; ni++) {
                float ox = ((acc[mi][ni][2 * h]     - mean) * inv * cgv[ni * 2]     + cbv[ni * 2])     * mk;
                float oy = ((acc[mi][ni][2 * h + 1] - mean) * inv * cgv[ni * 2 + 1] + cbv[ni * 2 + 1]) * mk;
                xo32[(size_t)grow * 64 + wn * 32 + ni * 4 + t] = pkh2(ox, oy);
            }
        }
}

// ---------------- pool partial: coalesced uint2 reads ----------------
__global__ void pool_partial_kernel(const __half* __restrict__ x, const float* __restrict__ nmask,
                                    float* __restrict__ pp, float* __restrict__ pm) {
    int blk = blockIdx.x;
    int b = blk >> 5, nc = blk & 31;
    int t = threadIdx.x;
    int g = t >> 5, l = t & 31;
    const uint2* xv = (const uint2*)x;
    float s0 = 0.f, s1 = 0.f, s2 = 0.f, s3 = 0.f;
    float m0 = -INFINITY, m1 = -INFINITY, m2 = -INFINITY, m3 = -INFINITY;
#pragma unroll 4
    for (int i = 0; i < 32; i++) {
        int n = nc * 256 + g * 32 + i;
        float mk = nmask[b * NN + n];
        uint2 u = xv[((size_t)(b * NN + n)) * 32 + l];
        float2 p = uph2(u.x), q = uph2(u.y);
        s0 += p.x * mk; s1 += p.y * mk; s2 += q.x * mk; s3 += q.y * mk;
        if (mk > 0.f) {
            m0 = fmaxf(m0, p.x * mk); m1 = fmaxf(m1, p.y * mk);
            m2 = fmaxf(m2, q.x * mk); m3 = fmaxf(m3, q.y * mk);
        }
    }
    __shared__ float sh[8][32][4];
    sh[g][l][0] = s0; sh[g][l][1] = s1; sh[g][l][2] = s2; sh[g][l][3] = s3;
    __syncthreads();
    if (g < 4) {
        int c = g * 32 + l;
        int ll = c >> 2, j = c & 3;
        float acc = 0.f;
#pragma unroll
        for (int k = 0; k < 8; k++) acc += sh[k][ll][j];
        pp[blk * 128 + c] = acc;
    }
    __syncthreads();
    sh[g][l][0] = m0; sh[g][l][1] = m1; sh[g][l][2] = m2; sh[g][l][3] = m3;
    __syncthreads();
    if (g < 4) {
        int c = g * 32 + l;
        int ll = c >> 2, j = c & 3;
        float acc = -INFINITY;
#pragma unroll
        for (int k = 0; k < 8; k++) acc = fmaxf(acc, sh[k][ll][j]);
        pm[blk * 128 + c] = acc;
    }
}

// ---------------- fused pool-final + MLP ----------------
__global__ void mlp_kernel(const float* __restrict__ pp, const float* __restrict__ pm,
                           const float* __restrict__ nmask,
                           const float* __restrict__ W1, const float* __restrict__ b1,
                           const float* __restrict__ W2, const float* __restrict__ b2,
                           float* __restrict__ out) {
    __shared__ float gs[256], hs[128], sc[256];
    int b = blockIdx.x, tid = threadIdx.x;

    // node-count reduction (all 256 threads)
    float cv = 0.f;
    for (int n = tid; n < NN; n += 256) cv += nmask[b * NN + n];
    sc[tid] = cv;
    __syncthreads();
    for (int d = 128; d; d >>= 1) {
        if (tid < d) sc[tid] += sc[tid + d];
        __syncthreads();
    }
    float cnt = fmaxf(sc[0], 1.f);

    // pool-final: threads 0-127 mean, 128-255 max
    {
        int c = tid & 127;
        if (tid < 128) {
            float s = 0.f;
#pragma unroll
            for (int k = 0; k < 32; k++) s += pp[(b * 32 + k) * 128 + c];
            gs[c] = s / cnt;
        } else {
            float mx = -INFINITY;
#pragma unroll
            for (int k = 0; k < 32; k++) mx = fmaxf(mx, pm[(b * 32 + k) * 128 + c]);
            gs[128 + c] = mx;
        }
    }
    __syncthreads();

    if (tid < 128) {
        float a = b1[tid];
        for (int k = 0; k < 256; k++) a = fmaf(gs[k], W1[k * 128 + tid], a);
        hs[tid] = fmaxf(a, 0.f);
    }
    __syncthreads();
    float a = b2[tid];
    for (int k = 0; k < 128; k++) a = fmaf(hs[k], W2[k * 256 + tid], a);
    out[b * 256 + tid] = a;
}

// ---------------- launch ----------------
extern "C" void kernel_launch(void* const* d_in, const int* in_sizes, int n_in,
                              void* d_out, int out_size) {
    const float* feats = (const float*)d_in[0];
    const int*   ei    = (const int*)d_in[1];
    const float* nmask = (const float*)d_in[2];
    const float* emask = (const float*)d_in[3];
    const float* inW   = (const float*)d_in[4];
    const float* inb   = (const float*)d_in[5];
    const float* sW    = (const float*)d_in[6];
    const float* sb    = (const float*)d_in[7];
    const float* nW    = (const float*)d_in[8];
    const float* nb    = (const float*)d_in[9];
    const float* lng   = (const float*)d_in[10];
    const float* lnb   = (const float*)d_in[11];
    const float* w1    = (const float*)d_in[12];
    const float* b1    = (const float*)d_in[13];
    const float* w2    = (const float*)d_in[14];
    const float* b2    = (const float*)d_in[15];

    __half *xh0, *xh1, *aggh;
    float *cw, *pp, *pm;
    uint32_t* wth;
    int *cnti, *off, *slot, *csrc;
    cudaGetSymbolAddress((void**)&xh0,  g_xh0);
    cudaGetSymbolAddress((void**)&xh1,  g_xh1);
    cudaGetSymbolAddress((void**)&aggh, g_aggh);
    cudaGetSymbolAddress((void**)&cnti, g_cnti);
    cudaGetSymbolAddress((void**)&off,  g_off);
    cudaGetSymbolAddress((void**)&slot, g_slot);
    cudaGetSymbolAddress((void**)&csrc, g_csrc);
    cudaGetSymbolAddress((void**)&cw,   g_cw);
    cudaGetSymbolAddress((void**)&wth,  g_wth);
    cudaGetSymbolAddress((void**)&pp,   g_pp);
    cudaGetSymbolAddress((void**)&pm,   g_pm);

    // side stream + fork/join events (created once, on the uncaptured correctness call)
    static cudaStream_t s1 = nullptr;
    static cudaEvent_t evFork = nullptr, evJoin = nullptr;
    if (s1 == nullptr) {
        cudaStreamCreateWithFlags(&s1, cudaStreamNonBlocking);
        cudaEventCreateWithFlags(&evFork, cudaEventDisableTiming);
        cudaEventCreateWithFlags(&evJoin, cudaEventDisableTiming);
    }

    // fork: side stream runs the input-projection chain
    cudaEventRecord(evFork, 0);
    cudaStreamWaitEvent(s1, evFork, 0);

    // main stream: CSR build chain
    cudaMemsetAsync(cnti, 0, MM * sizeof(int), 0);
    count_kernel<<<(ETOT + 255) / 256, 256>>>(ei, emask, cnti, slot);
    scan_kernel<<<64, 1024>>>(cnti, off);
    fill_kernel<<<(ETOT + 255) / 256, 256>>>(ei, emask, off, slot, csrc, cw);

    // side stream: weight pack + input GEMM
    wtrans_kernel<<<7, 256, 0, s1>>>(sW, nW, inW, wth);
    input_mma_kernel<<<MM / 128, 256, 0, s1>>>(feats, wth + WT6, inb, xh0);
    cudaEventRecord(evJoin, s1);
    cudaStreamWaitEvent(0, evJoin, 0);

    __half* xin = xh0;
    __half* xo  = xh1;
    for (int l = 0; l < 3; l++) {
        agg_csr_kernel<<<MM * 32 / 256, 256>>>(xin, off, csrc, cw, aggh);
        layer_mma_kernel<<<MM / 128, 256>>>(xin, aggh,
                                            wth + (size_t)(l * 2) * (HH * HH / 2),
                                            wth + (size_t)(l * 2 + 1) * (HH * HH / 2),
                                            sb + l * HH, nb + l * HH,
                                            lng + l * HH, lnb + l * HH,
                                            nmask, xo);
        __half* t = xin; xin = xo; xo = t;
    }

    pool_partial_kernel<<<256, 256>>>(xin, nmask, pp, pm);
    mlp_kernel<<<BB, 256>>>(pp, pm, nmask, w1, b1, w2, b2, (float*)d_out);
}

// round 16
// speedup vs baseline: 1.0524x; 1.0274x over previous
#include <cuda_runtime.h>
#include <cuda_fp16.h>
#include <math.h>
#include <stdint.h>

#define BB 8
#define NN 8192
#define EE 65536
#define FIN 64
#define HH 128
#define OUTD 256
#define MM (BB*NN)
#define ETOT (BB*EE)

// ---------------- scratch ----------------
__device__ __half g_xh0[MM*HH];
__device__ __half g_xh1[MM*HH];
__device__ __half g_aggh[MM*HH];
__device__ int    g_cnti[MM];
__device__ int    g_off[MM + 4];
__device__ int    g_slot[ETOT];
__device__ int    g_tstat[64];
__device__ int    g_csrc[ETOT];
__device__ float  g_cw[ETOT];
__device__ uint32_t g_wth[6*HH*HH/2 + HH*FIN/2];
__device__ float  g_pp[256*128];
__device__ float  g_pm[256*128];

// ---------------- fp16 helpers ----------------
__device__ __forceinline__ uint32_t pkh2(float x, float y) {
    __half2 h = __floats2half2_rn(x, y);
    return *reinterpret_cast<uint32_t*>(&h);
}
__device__ __forceinline__ float2 uph2(uint32_t v) {
    return __half22float2(*reinterpret_cast<const __half2*>(&v));
}
__device__ __forceinline__ void mma_f16(float* c, const uint32_t* a, uint32_t b0, uint32_t b1) {
    asm volatile("mma.sync.aligned.m16n8k16.row.col.f32.f16.f16.f32 "
                 "{%0,%1,%2,%3}, {%4,%5,%6,%7}, {%8,%9}, {%0,%1,%2,%3};"
                 : "+f"(c[0]), "+f"(c[1]), "+f"(c[2]), "+f"(c[3])
                 : "r"(a[0]), "r"(a[1]), "r"(a[2]), "r"(a[3]), "r"(b0), "r"(b1));
}

// ---------------- CSR build ----------------
__global__ void count_kernel(const int* __restrict__ ei, const float* __restrict__ emask,
                             int* __restrict__ cnti, int* __restrict__ slot) {
    if (blockIdx.x == 0 && threadIdx.x < 64) g_tstat[threadIdx.x] = 0;
    int e = blockIdx.x * blockDim.x + threadIdx.x;
    if (e >= ETOT) return;
    int b = e / EE, ee = e - b * EE;
    if (emask[e] != 0.f) {
        int tgt = ei[b * 2 * EE + EE + ee] + b * NN;
        slot[e] = atomicAdd(&cnti[tgt], 1);
    }
}

// single-pass scan with decoupled lookback (64 tiles of 1024)
__global__ void scan_kernel(const int* __restrict__ cnt, int* __restrict__ off) {
    __shared__ int sh[1024];
    __shared__ int exc;
    volatile int* tstat = g_tstat;
    const int b = blockIdx.x, t = threadIdx.x;
    const int g = b * 1024 + t;
    int v = cnt[g];
    sh[t] = v;
    __syncthreads();
    for (int d = 1; d < 1024; d <<= 1) {
        int u = (t >= d) ? sh[t - d] : 0;
        __syncthreads();
        sh[t] += u;
        __syncthreads();
    }
    const int total = sh[1023];
    if (t == 0) {
        if (b == 0) {
            __threadfence();
            tstat[0] = (2 << 28) | total;
            exc = 0;
        } else {
            __threadfence();
            tstat[b] = (1 << 28) | total;
            int ex = 0;
            int i = b - 1;
            while (i >= 0) {
                int s;
                do { s = tstat[i]; } while ((s >> 28) == 0);
                ex += s & 0x0FFFFFFF;
                if ((s >> 28) == 2) break;
                i--;
            }
            exc = ex;
            __threadfence();
            tstat[b] = (2 << 28) | (ex + total);
        }
    }
    __syncthreads();
    off[g] = sh[t] - v + exc;
    if (b == 63 && t == 1023) off[MM] = exc + total;
}

__global__ void fill_kernel(const int* __restrict__ ei, const float* __restrict__ emask,
                            const int* __restrict__ off, const int* __restrict__ slot,
                            int* __restrict__ csrc, float* __restrict__ cw) {
    int e = blockIdx.x * blockDim.x + threadIdx.x;
    if (e >= ETOT) return;
    int b = e / EE, ee = e - b * EE;
    float m = emask[e];
    if (m == 0.f) return;
    int src = ei[b * 2 * EE + ee] + b * NN;
    int tgt = ei[b * 2 * EE + EE + ee] + b * NN;
    int idx = off[tgt] + slot[e];
    csrc[idx] = src;
    cw[idx] = m;
}

// ---------------- weight transpose + fp16 pack (parallel, smem tile) ----------------
#define WT6 (6*HH*HH/2)
__global__ void wtrans_kernel(const float* __restrict__ sW, const float* __restrict__ nW,
                              const float* __restrict__ inW, uint32_t* __restrict__ wth) {
    __shared__ float tile[128][17];
    int blk = blockIdx.x;
    if (blk < 48) {
        int mat = blk >> 3, nch = blk & 7;
        int l = mat >> 1, pass = mat & 1;
        const float* src = (pass ? nW : sW) + (size_t)l * HH * HH;
        uint32_t* dst = wth + (size_t)mat * (HH * HH / 2);
        int n0 = nch * 16;
        // load 128(k) x 16(n) tile, row-contiguous reads
#pragma unroll
        for (int u = 0; u < 8; u++) {
            int idx = u * 256 + threadIdx.x;
            int k = idx >> 4, j = idx & 15;
            tile[k][j] = src[k * HH + n0 + j];
        }
        __syncthreads();
        // write packed fp16x2, coalesced over kk
#pragma unroll
        for (int u = 0; u < 4; u++) {
            int idx = u * 256 + threadIdx.x;
            int j = idx >> 6, kk = idx & 63;
            dst[(size_t)(n0 + j) * 64 + kk] = pkh2(tile[2 * kk][j], tile[2 * kk + 1][j]);
        }
    } else {
        // inW: [64 k][128 n] -> dst[n*32+kk]
        int nch = blk - 48;
        uint32_t* dst = wth + WT6;
        int n0 = nch * 16;
#pragma unroll
        for (int u = 0; u < 4; u++) {
            int idx = u * 256 + threadIdx.x;
            int k = idx >> 4, j = idx & 15;
            tile[k][j] = inW[k * HH + n0 + j];
        }
        __syncthreads();
#pragma unroll
        for (int u = 0; u < 2; u++) {
            int idx = u * 256 + threadIdx.x;
            int j = idx >> 5, kk = idx & 31;
            dst[(size_t)(n0 + j) * 32 + kk] = pkh2(tile[2 * kk][j], tile[2 * kk + 1][j]);
        }
    }
}

// ---------------- CSR aggregation: warp per node, fp16 gather ----------------
__global__ void agg_csr_kernel(const __half* __restrict__ xh, const int* __restrict__ off,
                               const int* __restrict__ csrc, const float* __restrict__ cw,
                               __half* __restrict__ outh) {
    int warp = (blockIdx.x * blockDim.x + threadIdx.x) >> 5;
    int lane = threadIdx.x & 31;
    if (warp >= MM) return;
    const uint2* xv = (const uint2*)xh;
    int beg = off[warp], end = off[warp + 1];
    float ax = 0.f, ay = 0.f, az = 0.f, aw = 0.f, ws = 0.f;
    int e = beg;
    for (; e + 2 <= end; e += 2) {
        int s0 = csrc[e], s1 = csrc[e + 1];
        float w0 = cw[e], w1 = cw[e + 1];
        uint2 u0 = xv[(size_t)s0 * 32 + lane];
        uint2 u1 = xv[(size_t)s1 * 32 + lane];
        float2 p0 = uph2(u0.x), q0 = uph2(u0.y);
        float2 p1 = uph2(u1.x), q1 = uph2(u1.y);
        ax += p0.x * w0 + p1.x * w1;
        ay += p0.y * w0 + p1.y * w1;
        az += q0.x * w0 + q1.x * w1;
        aw += q0.y * w0 + q1.y * w1;
        ws += w0 + w1;
    }
    if (e < end) {
        int s0 = csrc[e];
        float w0 = cw[e];
        uint2 u0 = xv[(size_t)s0 * 32 + lane];
        float2 p0 = uph2(u0.x), q0 = uph2(u0.y);
        ax += p0.x * w0; ay += p0.y * w0; az += q0.x * w0; aw += q0.y * w0;
        ws += w0;
    }
    float inv = 1.0f / fmaxf(ws, 1.0f);
    uint2 o;
    o.x = pkh2(ax * inv, ay * inv);
    o.y = pkh2(az * inv, aw * inv);
    ((uint2*)outh)[(size_t)warp * 32 + lane] = o;
}

// ================= fp16 HMMA GEMMs: CTA 128x128, warps 4(M) x 2(N) =================
#define PSTR 20

// ---------------- input GEMM: xh0 = relu(feats @ inW + inb) ----------------
__global__ void __launch_bounds__(256, 2)
input_mma_kernel(const float* __restrict__ A, const uint32_t* __restrict__ Wh,
                 const float* __restrict__ bias, __half* __restrict__ xout) {
    __shared__ __align__(16) uint32_t As[128 * PSTR];
    __shared__ __align__(16) uint32_t Bs[128 * PSTR];

    const int tid = threadIdx.x;
    const int wid = tid >> 5, lane = tid & 31;
    const int wm = wid & 3, wn = wid >> 2;
    const int g = lane >> 2, t = lane & 3;
    const int m0 = blockIdx.x * 128;

    float acc[2][8][4];
#pragma unroll
    for (int mi = 0; mi < 2; mi++)
#pragma unroll
        for (int ni = 0; ni < 8; ni++)
#pragma unroll
            for (int c = 0; c < 4; c++) acc[mi][ni][c] = 0.f;

    const float* Asrc = A + (size_t)m0 * FIN;

#pragma unroll 1
    for (int ch = 0; ch < 2; ch++) {
        __syncthreads();
#pragma unroll
        for (int u = 0; u < 4; u++) {
            int idx = u * 256 + tid;
            int row = idx >> 3, c4 = idx & 7;
            float4 v = *(const float4*)&Asrc[(size_t)row * FIN + ch * 32 + c4 * 4];
            uint2 o = make_uint2(pkh2(v.x, v.y), pkh2(v.z, v.w));
            *(uint2*)&As[row * PSTR + c4 * 2] = o;
        }
#pragma unroll
        for (int u = 0; u < 2; u++) {
            int idx = u * 256 + tid;
            int row = idx >> 2, q = idx & 3;
            uint4 w = *(const uint4*)&Wh[(size_t)row * 32 + ch * 16 + q * 4];
            *(uint4*)&Bs[row * PSTR + q * 4] = w;
        }
        __syncthreads();
#pragma unroll
        for (int ks = 0; ks < 2; ks++) {
            uint32_t a[2][4], b[8][2];
#pragma unroll
            for (int mi = 0; mi < 2; mi++) {
                int base = (wm * 32 + mi * 16 + g) * PSTR + ks * 8 + t;
                a[mi][0] = As[base];
                a[mi][1] = As[base + 8 * PSTR];
                a[mi][2] = As[base + 4];
                a[mi][3] = As[base + 8 * PSTR + 4];
            }
#pragma unroll
            for (int ni = 0; ni < 8; ni++) {
                int nb = (wn * 64 + ni * 8 + g) * PSTR + ks * 8 + t;
                b[ni][0] = Bs[nb];
                b[ni][1] = Bs[nb + 4];
            }
#pragma unroll
            for (int mi = 0; mi < 2; mi++)
#pragma unroll
                for (int ni = 0; ni < 8; ni++)
                    mma_f16(acc[mi][ni], a[mi], b[ni][0], b[ni][1]);
        }
    }

    float cb[16];
#pragma unroll
    for (int ni = 0; ni < 8; ni++)
#pragma unroll
        for (int j = 0; j < 2; j++)
            cb[ni * 2 + j] = bias[wn * 64 + ni * 8 + 2 * t + j];
    uint32_t* xo32 = (uint32_t*)xout;
#pragma unroll
    for (int mi = 0; mi < 2; mi++)
#pragma unroll
        for (int h = 0; h < 2; h++) {
            int grow = m0 + wm * 32 + mi * 16 + g + 8 * h;
#pragma unroll
            for (int ni = 0; ni < 8; ni++) {
                float ox = fmaxf(acc[mi][ni][2 * h]     + cb[ni * 2],     0.f);
                float oy = fmaxf(acc[mi][ni][2 * h + 1] + cb[ni * 2 + 1], 0.f);
                xo32[(size_t)grow * 64 + wn * 32 + ni * 4 + t] = pkh2(ox, oy);
            }
        }
}

// ---------------- fused layer GEMM (double-buffered smem, 1 sync/chunk) ----------------
__global__ void __launch_bounds__(256, 2)
layer_mma_kernel(const __half* __restrict__ xh, const __half* __restrict__ aggh,
                 const uint32_t* __restrict__ Wsh, const uint32_t* __restrict__ Wnh,
                 const float* __restrict__ bsb, const float* __restrict__ bnb,
                 const float* __restrict__ lng, const float* __restrict__ lnb,
                 const float* __restrict__ nmask, __half* __restrict__ xout) {
    __shared__ __align__(16) uint32_t As[2][128 * PSTR];
    __shared__ __align__(16) uint32_t Bs[2][128 * PSTR];
    __shared__ float red[128][4];

    const int tid = threadIdx.x;
    const int wid = tid >> 5, lane = tid & 31;
    const int wm = wid & 3, wn = wid >> 2;
    const int g = lane >> 2, t = lane & 3;
    const int m0 = blockIdx.x * 128;
    const int srow = tid >> 2, sq = tid & 3;

    float acc[2][8][4];
#pragma unroll
    for (int mi = 0; mi < 2; mi++)
#pragma unroll
        for (int ni = 0; ni < 8; ni++)
#pragma unroll
            for (int c = 0; c < 4; c++) acc[mi][ni][c] = 0.f;

    const uint32_t* Apass[2] = {(const uint32_t*)xh + (size_t)m0 * 64,
                                (const uint32_t*)aggh + (size_t)m0 * 64};
    const uint32_t* Bpass[2] = {Wsh, Wnh};

    uint4 pva[2], pvb[2];
#pragma unroll
    for (int u = 0; u < 2; u++) {
        int row = srow + u * 64;
        pva[u] = *(const uint4*)&Apass[0][(size_t)row * 64 + sq * 4];
        pvb[u] = *(const uint4*)&Bpass[0][(size_t)row * 64 + sq * 4];
    }
#pragma unroll
    for (int u = 0; u < 2; u++) {
        int row = srow + u * 64;
        *(uint4*)&As[0][row * PSTR + sq * 4] = pva[u];
        *(uint4*)&Bs[0][row * PSTR + sq * 4] = pvb[u];
    }
#pragma unroll
    for (int u = 0; u < 2; u++) {
        int row = srow + u * 64;
        pva[u] = *(const uint4*)&Apass[0][(size_t)row * 64 + 16 + sq * 4];
        pvb[u] = *(const uint4*)&Bpass[0][(size_t)row * 64 + 16 + sq * 4];
    }
    __syncthreads();

#pragma unroll 1
    for (int ch = 0; ch < 8; ch++) {
        const int buf = ch & 1;
        if (ch < 7) {
#pragma unroll
            for (int u = 0; u < 2; u++) {
                int row = srow + u * 64;
                *(uint4*)&As[buf ^ 1][row * PSTR + sq * 4] = pva[u];
                *(uint4*)&Bs[buf ^ 1][row * PSTR + sq * 4] = pvb[u];
            }
        }
        if (ch < 6) {
            int nc = ch + 2;
            const uint32_t* A_ = Apass[nc >> 2];
            const uint32_t* B_ = Bpass[nc >> 2];
            int koff = (nc & 3) * 16;
#pragma unroll
            for (int u = 0; u < 2; u++) {
                int row = srow + u * 64;
                pva[u] = *(const uint4*)&A_[(size_t)row * 64 + koff + sq * 4];
                pvb[u] = *(const uint4*)&B_[(size_t)row * 64 + koff + sq * 4];
            }
        }
#pragma unroll
        for (int ks = 0; ks < 2; ks++) {
            uint32_t a[2][4], b[8][2];
#pragma unroll
            for (int mi = 0; mi < 2; mi++) {
                int base = (wm * 32 + mi * 16 + g) * PSTR + ks * 8 + t;
                a[mi][0] = As[buf][base];
                a[mi][1] = As[buf][base + 8 * PSTR];
                a[mi][2] = As[buf][base + 4];
                a[mi][3] = As[buf][base + 8 * PSTR + 4];
            }
#pragma unroll
            for (int ni = 0; ni < 8; ni++) {
                int nb = (wn * 64 + ni * 8 + g) * PSTR + ks * 8 + t;
                b[ni][0] = Bs[buf][nb];
                b[ni][1] = Bs[buf][nb + 4];
            }
#pragma unroll
            for (int mi = 0; mi < 2; mi++)
#pragma unroll
                for (int ni = 0; ni < 8; ni++)
                    mma_f16(acc[mi][ni], a[mi], b[ni][0], b[ni][1]);
        }
        __syncthreads();
    }

    // ---- epilogue: bias + relu + layernorm + mask -> fp16 ----
    float cb[16], cgv[16], cbv[16];
#pragma unroll
    for (int ni = 0; ni < 8; ni++)
#pragma unroll
        for (int j = 0; j < 2; j++) {
            int c = wn * 64 + ni * 8 + 2 * t + j;
            cb[ni * 2 + j]  = bsb[c] + bnb[c];
            cgv[ni * 2 + j] = lng[c];
            cbv[ni * 2 + j] = lnb[c];
        }
#pragma unroll
    for (int mi = 0; mi < 2; mi++)
#pragma unroll
        for (int h = 0; h < 2; h++) {
            float s1 = 0.f, s2 = 0.f;
#pragma unroll
            for (int ni = 0; ni < 8; ni++)
#pragma unroll
                for (int j = 0; j < 2; j++) {
                    float v = fmaxf(acc[mi][ni][2 * h + j] + cb[ni * 2 + j], 0.f);
                    acc[mi][ni][2 * h + j] = v;
                    s1 += v;
                    s2 += v * v;
                }
            s1 += __shfl_xor_sync(0xffffffffu, s1, 1);
            s1 += __shfl_xor_sync(0xffffffffu, s1, 2);
            s2 += __shfl_xor_sync(0xffffffffu, s2, 1);
            s2 += __shfl_xor_sync(0xffffffffu, s2, 2);
            if (t == 0) {
                int row = wm * 32 + mi * 16 + g + 8 * h;
                red[row][wn * 2]     = s1;
                red[row][wn * 2 + 1] = s2;
            }
        }
    __syncthreads();
    uint32_t* xo32 = (uint32_t*)xout;
#pragma unroll
    for (int mi = 0; mi < 2; mi++)
#pragma unroll
        for (int h = 0; h < 2; h++) {
            int row = wm * 32 + mi * 16 + g + 8 * h;
            float s1 = red[row][0] + red[row][2];
            float s2 = red[row][1] + red[row][3];
            float mean = s1 * (1.0f / 128.0f);
            float var = fmaxf(s2 * (1.0f / 128.0f) - mean * mean, 0.f);
            float inv = rsqrtf(var + 1e-5f);
            int grow = m0 + row;
            float mk = nmask[grow];
#pragma unroll
            for (int ni = 0; ni < 8; ni++) {
                float ox = ((acc[mi][ni][2 * h]     - mean) * inv * cgv[ni * 2]     + cbv[ni * 2])     * mk;
                float oy = ((acc[mi][ni][2 * h + 1] - mean) * inv * cgv[ni * 2 + 1] + cbv[ni * 2 + 1]) * mk;
                xo32[(size_t)grow * 64 + wn * 32 + ni * 4 + t] = pkh2(ox, oy);
            }
        }
}

// ---------------- pool partial: coalesced uint2 reads ----------------
__global__ void pool_partial_kernel(const __half* __restrict__ x, const float* __restrict__ nmask,
                                    float* __restrict__ pp, float* __restrict__ pm) {
    int blk = blockIdx.x;
    int b = blk >> 5, nc = blk & 31;
    int t = threadIdx.x;
    int g = t >> 5, l = t & 31;
    const uint2* xv = (const uint2*)x;
    float s0 = 0.f, s1 = 0.f, s2 = 0.f, s3 = 0.f;
    float m0 = -INFINITY, m1 = -INFINITY, m2 = -INFINITY, m3 = -INFINITY;
#pragma unroll 4
    for (int i = 0; i < 32; i++) {
        int n = nc * 256 + g * 32 + i;
        float mk = nmask[b * NN + n];
        uint2 u = xv[((size_t)(b * NN + n)) * 32 + l];
        float2 p = uph2(u.x), q = uph2(u.y);
        s0 += p.x * mk; s1 += p.y * mk; s2 += q.x * mk; s3 += q.y * mk;
        if (mk > 0.f) {
            m0 = fmaxf(m0, p.x * mk); m1 = fmaxf(m1, p.y * mk);
            m2 = fmaxf(m2, q.x * mk); m3 = fmaxf(m3, q.y * mk);
        }
    }
    __shared__ float sh[8][32][4];
    sh[g][l][0] = s0; sh[g][l][1] = s1; sh[g][l][2] = s2; sh[g][l][3] = s3;
    __syncthreads();
    if (g < 4) {
        int c = g * 32 + l;
        int ll = c >> 2, j = c & 3;
        float acc = 0.f;
#pragma unroll
        for (int k = 0; k < 8; k++) acc += sh[k][ll][j];
        pp[blk * 128 + c] = acc;
    }
    __syncthreads();
    sh[g][l][0] = m0; sh[g][l][1] = m1; sh[g][l][2] = m2; sh[g][l][3] = m3;
    __syncthreads();
    if (g < 4) {
        int c = g * 32 + l;
        int ll = c >> 2, j = c & 3;
        float acc = -INFINITY;
#pragma unroll
        for (int k = 0; k < 8; k++) acc = fmaxf(acc, sh[k][ll][j]);
        pm[blk * 128 + c] = acc;
    }
}

// ---------------- fused pool-final + MLP ----------------
__global__ void mlp_kernel(const float* __restrict__ pp, const float* __restrict__ pm,
                           const float* __restrict__ nmask,
                           const float* __restrict__ W1, const float* __restrict__ b1,
                           const float* __restrict__ W2, const float* __restrict__ b2,
                           float* __restrict__ out) {
    __shared__ float gs[256], hs[128], sc[256];
    int b = blockIdx.x, tid = threadIdx.x;

    float cv = 0.f;
    for (int n = tid; n < NN; n += 256) cv += nmask[b * NN + n];
    sc[tid] = cv;
    __syncthreads();
    for (int d = 128; d; d >>= 1) {
        if (tid < d) sc[tid] += sc[tid + d];
        __syncthreads();
    }
    float cnt = fmaxf(sc[0], 1.f);

    {
        int c = tid & 127;
        if (tid < 128) {
            float s = 0.f;
#pragma unroll
            for (int k = 0; k < 32; k++) s += pp[(b * 32 + k) * 128 + c];
            gs[c] = s / cnt;
        } else {
            float mx = -INFINITY;
#pragma unroll
            for (int k = 0; k < 32; k++) mx = fmaxf(mx, pm[(b * 32 + k) * 128 + c]);
            gs[128 + c] = mx;
        }
    }
    __syncthreads();

    if (tid < 128) {
        float a = b1[tid];
        for (int k = 0; k < 256; k++) a = fmaf(gs[k], W1[k * 128 + tid], a);
        hs[tid] = fmaxf(a, 0.f);
    }
    __syncthreads();
    float a = b2[tid];
    for (int k = 0; k < 128; k++) a = fmaf(hs[k], W2[k * 256 + tid], a);
    out[b * 256 + tid] = a;
}

// ---------------- launch ----------------
extern "C" void kernel_launch(void* const* d_in, const int* in_sizes, int n_in,
                              void* d_out, int out_size) {
    const float* feats = (const float*)d_in[0];
    const int*   ei    = (const int*)d_in[1];
    const float* nmask = (const float*)d_in[2];
    const float* emask = (const float*)d_in[3];
    const float* inW   = (const float*)d_in[4];
    const float* inb   = (const float*)d_in[5];
    const float* sW    = (const float*)d_in[6];
    const float* sb    = (const float*)d_in[7];
    const float* nW    = (const float*)d_in[8];
    const float* nb    = (const float*)d_in[9];
    const float* lng   = (const float*)d_in[10];
    const float* lnb   = (const float*)d_in[11];
    const float* w1    = (const float*)d_in[12];
    const float* b1    = (const float*)d_in[13];
    const float* w2    = (const float*)d_in[14];
    const float* b2    = (const float*)d_in[15];

    __half *xh0, *xh1, *aggh;
    float *cw, *pp, *pm;
    uint32_t* wth;
    int *cnti, *off, *slot, *csrc;
    cudaGetSymbolAddress((void**)&xh0,  g_xh0);
    cudaGetSymbolAddress((void**)&xh1,  g_xh1);
    cudaGetSymbolAddress((void**)&aggh, g_aggh);
    cudaGetSymbolAddress((void**)&cnti, g_cnti);
    cudaGetSymbolAddress((void**)&off,  g_off);
    cudaGetSymbolAddress((void**)&slot, g_slot);
    cudaGetSymbolAddress((void**)&csrc, g_csrc);
    cudaGetSymbolAddress((void**)&cw,   g_cw);
    cudaGetSymbolAddress((void**)&wth,  g_wth);
    cudaGetSymbolAddress((void**)&pp,   g_pp);
    cudaGetSymbolAddress((void**)&pm,   g_pm);

    static cudaStream_t s1 = nullptr;
    static cudaEvent_t evFork = nullptr, evJoin = nullptr;
    if (s1 == nullptr) {
        cudaStreamCreateWithFlags(&s1, cudaStreamNonBlocking);
        cudaEventCreateWithFlags(&evFork, cudaEventDisableTiming);
        cudaEventCreateWithFlags(&evJoin, cudaEventDisableTiming);
    }

    // fork: side stream runs the input-projection chain
    cudaEventRecord(evFork, 0);
    cudaStreamWaitEvent(s1, evFork, 0);

    // main stream: CSR build chain
    cudaMemsetAsync(cnti, 0, MM * sizeof(int), 0);
    count_kernel<<<(ETOT + 255) / 256, 256>>>(ei, emask, cnti, slot);
    scan_kernel<<<64, 1024>>>(cnti, off);
    fill_kernel<<<(ETOT + 255) / 256, 256>>>(ei, emask, off, slot, csrc, cw);

    // side stream: weight pack + input GEMM
    wtrans_kernel<<<56, 256, 0, s1>>>(sW, nW, inW, wth);
    input_mma_kernel<<<MM / 128, 256, 0, s1>>>(feats, wth + WT6, inb, xh0);
    cudaEventRecord(evJoin, s1);
    cudaStreamWaitEvent(0, evJoin, 0);

    __half* xin = xh0;
    __half* xo  = xh1;
    for (int l = 0; l < 3; l++) {
        agg_csr_kernel<<<MM * 32 / 256, 256>>>(xin, off, csrc, cw, aggh);
        layer_mma_kernel<<<MM / 128, 256>>>(xin, aggh,
                                            wth + (size_t)(l * 2) * (HH * HH / 2),
                                            wth + (size_t)(l * 2 + 1) * (HH * HH / 2),
                                            sb + l * HH, nb + l * HH,
                                            lng + l * HH, lnb + l * HH,
                                            nmask, xo);
        __half* t = xin; xin = xo; xo = t;
    }

    pool_partial_kernel<<<256, 256>>>(xin, nmask, pp, pm);
    mlp_kernel<<<BB, 256>>>(pp, pm, nmask, w1, b1, w2, b2, (float*)d_out);
}

// round 17
// speedup vs baseline: 1.0722x; 1.0188x over previous
#include <cuda_runtime.h>
#include <cuda_fp16.h>
#include <math.h>
#include <stdint.h>

#define BB 8
#define NN 8192
#define EE 65536
#define FIN 64
#define HH 128
#define OUTD 256
#define MM (BB*NN)
#define ETOT (BB*EE)

// ---------------- scratch ----------------
__device__ __half g_xh0[MM*HH];
__device__ __half g_xh1[MM*HH];
__device__ __half g_aggh[MM*HH];
__device__ int    g_cnti[MM];
__device__ int    g_off[MM + 4];
__device__ int    g_slot[ETOT];
__device__ int    g_tstat[64];
__device__ int    g_csrc[ETOT];
__device__ float  g_cw[ETOT];
__device__ uint32_t g_wth[6*HH*HH/2 + HH*FIN/2];
__device__ float  g_pp[256*128];
__device__ float  g_pm[256*128];

// ---------------- fp16 helpers ----------------
__device__ __forceinline__ uint32_t pkh2(float x, float y) {
    __half2 h = __floats2half2_rn(x, y);
    return *reinterpret_cast<uint32_t*>(&h);
}
__device__ __forceinline__ float2 uph2(uint32_t v) {
    return __half22float2(*reinterpret_cast<const __half2*>(&v));
}
__device__ __forceinline__ void mma_f16(float* c, const uint32_t* a, uint32_t b0, uint32_t b1) {
    asm volatile("mma.sync.aligned.m16n8k16.row.col.f32.f16.f16.f32 "
                 "{%0,%1,%2,%3}, {%4,%5,%6,%7}, {%8,%9}, {%0,%1,%2,%3};"
                 : "+f"(c[0]), "+f"(c[1]), "+f"(c[2]), "+f"(c[3])
                 : "r"(a[0]), "r"(a[1]), "r"(a[2]), "r"(a[3]), "r"(b0), "r"(b1));
}

// ---------------- CSR build ----------------
__global__ void count_kernel(const int* __restrict__ ei, const float* __restrict__ emask,
                             int* __restrict__ cnti, int* __restrict__ slot) {
    if (blockIdx.x == 0 && threadIdx.x < 64) g_tstat[threadIdx.x] = 0;
    int e = blockIdx.x * blockDim.x + threadIdx.x;
    if (e >= ETOT) return;
    int b = e / EE, ee = e - b * EE;
    if (emask[e] != 0.f) {
        int tgt = ei[b * 2 * EE + EE + ee] + b * NN;
        slot[e] = atomicAdd(&cnti[tgt], 1);
    }
}

// single-pass scan with decoupled lookback (64 tiles of 1024)
__global__ void scan_kernel(const int* __restrict__ cnt, int* __restrict__ off) {
    __shared__ int sh[1024];
    __shared__ int exc;
    volatile int* tstat = g_tstat;
    const int b = blockIdx.x, t = threadIdx.x;
    const int g = b * 1024 + t;
    int v = cnt[g];
    sh[t] = v;
    __syncthreads();
    for (int d = 1; d < 1024; d <<= 1) {
        int u = (t >= d) ? sh[t - d] : 0;
        __syncthreads();
        sh[t] += u;
        __syncthreads();
    }
    const int total = sh[1023];
    if (t == 0) {
        if (b == 0) {
            __threadfence();
            tstat[0] = (2 << 28) | total;
            exc = 0;
        } else {
            __threadfence();
            tstat[b] = (1 << 28) | total;
            int ex = 0;
            int i = b - 1;
            while (i >= 0) {
                int s;
                do { s = tstat[i]; } while ((s >> 28) == 0);
                ex += s & 0x0FFFFFFF;
                if ((s >> 28) == 2) break;
                i--;
            }
            exc = ex;
            __threadfence();
            tstat[b] = (2 << 28) | (ex + total);
        }
    }
    __syncthreads();
    off[g] = sh[t] - v + exc;
    if (b == 63 && t == 1023) off[MM] = exc + total;
}

__global__ void fill_kernel(const int* __restrict__ ei, const float* __restrict__ emask,
                            const int* __restrict__ off, const int* __restrict__ slot,
                            int* __restrict__ csrc, float* __restrict__ cw) {
    int e = blockIdx.x * blockDim.x + threadIdx.x;
    if (e >= ETOT) return;
    int b = e / EE, ee = e - b * EE;
    float m = emask[e];
    if (m == 0.f) return;
    int src = ei[b * 2 * EE + ee] + b * NN;
    int tgt = ei[b * 2 * EE + EE + ee] + b * NN;
    int idx = off[tgt] + slot[e];
    csrc[idx] = src;
    cw[idx] = m;
}

// ---------------- weight transpose + fp16 pack (parallel, smem tile) ----------------
#define WT6 (6*HH*HH/2)
__global__ void wtrans_kernel(const float* __restrict__ sW, const float* __restrict__ nW,
                              const float* __restrict__ inW, uint32_t* __restrict__ wth) {
    __shared__ float tile[128][17];
    int blk = blockIdx.x;
    if (blk < 48) {
        int mat = blk >> 3, nch = blk & 7;
        int l = mat >> 1, pass = mat & 1;
        const float* src = (pass ? nW : sW) + (size_t)l * HH * HH;
        uint32_t* dst = wth + (size_t)mat * (HH * HH / 2);
        int n0 = nch * 16;
#pragma unroll
        for (int u = 0; u < 8; u++) {
            int idx = u * 256 + threadIdx.x;
            int k = idx >> 4, j = idx & 15;
            tile[k][j] = src[k * HH + n0 + j];
        }
        __syncthreads();
#pragma unroll
        for (int u = 0; u < 4; u++) {
            int idx = u * 256 + threadIdx.x;
            int j = idx >> 6, kk = idx & 63;
            dst[(size_t)(n0 + j) * 64 + kk] = pkh2(tile[2 * kk][j], tile[2 * kk + 1][j]);
        }
    } else {
        int nch = blk - 48;
        uint32_t* dst = wth + WT6;
        int n0 = nch * 16;
#pragma unroll
        for (int u = 0; u < 4; u++) {
            int idx = u * 256 + threadIdx.x;
            int k = idx >> 4, j = idx & 15;
            tile[k][j] = inW[k * HH + n0 + j];
        }
        __syncthreads();
#pragma unroll
        for (int u = 0; u < 2; u++) {
            int idx = u * 256 + threadIdx.x;
            int j = idx >> 5, kk = idx & 31;
            dst[(size_t)(n0 + j) * 32 + kk] = pkh2(tile[2 * kk][j], tile[2 * kk + 1][j]);
        }
    }
}

// ---------------- CSR aggregation: warp per node, 4-edge MLP ----------------
__global__ void agg_csr_kernel(const __half* __restrict__ xh, const int* __restrict__ off,
                               const int* __restrict__ csrc, const float* __restrict__ cw,
                               __half* __restrict__ outh) {
    int warp = (blockIdx.x * blockDim.x + threadIdx.x) >> 5;
    int lane = threadIdx.x & 31;
    if (warp >= MM) return;
    const uint2* xv = (const uint2*)xh;
    int beg = off[warp], end = off[warp + 1];
    float ax = 0.f, ay = 0.f, az = 0.f, aw = 0.f, ws = 0.f;
    int e = beg;
    for (; e + 4 <= end; e += 4) {
        int s0 = csrc[e], s1 = csrc[e + 1], s2 = csrc[e + 2], s3 = csrc[e + 3];
        float w0 = cw[e], w1 = cw[e + 1], w2 = cw[e + 2], w3 = cw[e + 3];
        uint2 u0 = xv[(size_t)s0 * 32 + lane];
        uint2 u1 = xv[(size_t)s1 * 32 + lane];
        uint2 u2 = xv[(size_t)s2 * 32 + lane];
        uint2 u3 = xv[(size_t)s3 * 32 + lane];
        float2 p0 = uph2(u0.x), q0 = uph2(u0.y);
        float2 p1 = uph2(u1.x), q1 = uph2(u1.y);
        float2 p2 = uph2(u2.x), q2 = uph2(u2.y);
        float2 p3 = uph2(u3.x), q3 = uph2(u3.y);
        ax += p0.x * w0; ay += p0.y * w0; az += q0.x * w0; aw += q0.y * w0; ws += w0;
        ax += p1.x * w1; ay += p1.y * w1; az += q1.x * w1; aw += q1.y * w1; ws += w1;
        ax += p2.x * w2; ay += p2.y * w2; az += q2.x * w2; aw += q2.y * w2; ws += w2;
        ax += p3.x * w3; ay += p3.y * w3; az += q3.x * w3; aw += q3.y * w3; ws += w3;
    }
    for (; e < end; e++) {
        int s0 = csrc[e];
        float w0 = cw[e];
        uint2 u0 = xv[(size_t)s0 * 32 + lane];
        float2 p0 = uph2(u0.x), q0 = uph2(u0.y);
        ax += p0.x * w0; ay += p0.y * w0; az += q0.x * w0; aw += q0.y * w0;
        ws += w0;
    }
    float inv = 1.0f / fmaxf(ws, 1.0f);
    uint2 o;
    o.x = pkh2(ax * inv, ay * inv);
    o.y = pkh2(az * inv, aw * inv);
    ((uint2*)outh)[(size_t)warp * 32 + lane] = o;
}

// ================= fp16 HMMA GEMMs: CTA 128x128, warps 4(M) x 2(N) =================
#define PSTR 20

// ---------------- input GEMM: xh0 = relu(feats @ inW + inb) ----------------
__global__ void __launch_bounds__(256, 2)
input_mma_kernel(const float* __restrict__ A, const uint32_t* __restrict__ Wh,
                 const float* __restrict__ bias, __half* __restrict__ xout) {
    __shared__ __align__(16) uint32_t As[128 * PSTR];
    __shared__ __align__(16) uint32_t Bs[128 * PSTR];

    const int tid = threadIdx.x;
    const int wid = tid >> 5, lane = tid & 31;
    const int wm = wid & 3, wn = wid >> 2;
    const int g = lane >> 2, t = lane & 3;
    const int m0 = blockIdx.x * 128;

    float acc[2][8][4];
#pragma unroll
    for (int mi = 0; mi < 2; mi++)
#pragma unroll
        for (int ni = 0; ni < 8; ni++)
#pragma unroll
            for (int c = 0; c < 4; c++) acc[mi][ni][c] = 0.f;

    const float* Asrc = A + (size_t)m0 * FIN;

#pragma unroll 1
    for (int ch = 0; ch < 2; ch++) {
        __syncthreads();
#pragma unroll
        for (int u = 0; u < 4; u++) {
            int idx = u * 256 + tid;
            int row = idx >> 3, c4 = idx & 7;
            float4 v = *(const float4*)&Asrc[(size_t)row * FIN + ch * 32 + c4 * 4];
            uint2 o = make_uint2(pkh2(v.x, v.y), pkh2(v.z, v.w));
            *(uint2*)&As[row * PSTR + c4 * 2] = o;
        }
#pragma unroll
        for (int u = 0; u < 2; u++) {
            int idx = u * 256 + tid;
            int row = idx >> 2, q = idx & 3;
            uint4 w = *(const uint4*)&Wh[(size_t)row * 32 + ch * 16 + q * 4];
            *(uint4*)&Bs[row * PSTR + q * 4] = w;
        }
        __syncthreads();
#pragma unroll
        for (int ks = 0; ks < 2; ks++) {
            uint32_t a[2][4], b[8][2];
#pragma unroll
            for (int mi = 0; mi < 2; mi++) {
                int base = (wm * 32 + mi * 16 + g) * PSTR + ks * 8 + t;
                a[mi][0] = As[base];
                a[mi][1] = As[base + 8 * PSTR];
                a[mi][2] = As[base + 4];
                a[mi][3] = As[base + 8 * PSTR + 4];
            }
#pragma unroll
            for (int ni = 0; ni < 8; ni++) {
                int nb = (wn * 64 + ni * 8 + g) * PSTR + ks * 8 + t;
                b[ni][0] = Bs[nb];
                b[ni][1] = Bs[nb + 4];
            }
#pragma unroll
            for (int mi = 0; mi < 2; mi++)
#pragma unroll
                for (int ni = 0; ni < 8; ni++)
                    mma_f16(acc[mi][ni], a[mi], b[ni][0], b[ni][1]);
        }
    }

    float cb[16];
#pragma unroll
    for (int ni = 0; ni < 8; ni++)
#pragma unroll
        for (int j = 0; j < 2; j++)
            cb[ni * 2 + j] = bias[wn * 64 + ni * 8 + 2 * t + j];
    uint32_t* xo32 = (uint32_t*)xout;
#pragma unroll
    for (int mi = 0; mi < 2; mi++)
#pragma unroll
        for (int h = 0; h < 2; h++) {
            int grow = m0 + wm * 32 + mi * 16 + g + 8 * h;
#pragma unroll
            for (int ni = 0; ni < 8; ni++) {
                float ox = fmaxf(acc[mi][ni][2 * h]     + cb[ni * 2],     0.f);
                float oy = fmaxf(acc[mi][ni][2 * h + 1] + cb[ni * 2 + 1], 0.f);
                xo32[(size_t)grow * 64 + wn * 32 + ni * 4 + t] = pkh2(ox, oy);
            }
        }
}

// ---------------- fused layer GEMM (double-buffered smem, 1 sync/chunk) ----------------
__global__ void __launch_bounds__(256, 2)
layer_mma_kernel(const __half* __restrict__ xh, const __half* __restrict__ aggh,
                 const uint32_t* __restrict__ Wsh, const uint32_t* __restrict__ Wnh,
                 const float* __restrict__ bsb, const float* __restrict__ bnb,
                 const float* __restrict__ lng, const float* __restrict__ lnb,
                 const float* __restrict__ nmask, __half* __restrict__ xout) {
    __shared__ __align__(16) uint32_t As[2][128 * PSTR];
    __shared__ __align__(16) uint32_t Bs[2][128 * PSTR];
    __shared__ float red[128][4];

    const int tid = threadIdx.x;
    const int wid = tid >> 5, lane = tid & 31;
    const int wm = wid & 3, wn = wid >> 2;
    const int g = lane >> 2, t = lane & 3;
    const int m0 = blockIdx.x * 128;
    const int srow = tid >> 2, sq = tid & 3;

    float acc[2][8][4];
#pragma unroll
    for (int mi = 0; mi < 2; mi++)
#pragma unroll
        for (int ni = 0; ni < 8; ni++)
#pragma unroll
            for (int c = 0; c < 4; c++) acc[mi][ni][c] = 0.f;

    const uint32_t* Apass[2] = {(const uint32_t*)xh + (size_t)m0 * 64,
                                (const uint32_t*)aggh + (size_t)m0 * 64};
    const uint32_t* Bpass[2] = {Wsh, Wnh};

    uint4 pva[2], pvb[2];
#pragma unroll
    for (int u = 0; u < 2; u++) {
        int row = srow + u * 64;
        pva[u] = *(const uint4*)&Apass[0][(size_t)row * 64 + sq * 4];
        pvb[u] = *(const uint4*)&Bpass[0][(size_t)row * 64 + sq * 4];
    }
#pragma unroll
    for (int u = 0; u < 2; u++) {
        int row = srow + u * 64;
        *(uint4*)&As[0][row * PSTR + sq * 4] = pva[u];
        *(uint4*)&Bs[0][row * PSTR + sq * 4] = pvb[u];
    }
#pragma unroll
    for (int u = 0; u < 2; u++) {
        int row = srow + u * 64;
        pva[u] = *(const uint4*)&Apass[0][(size_t)row * 64 + 16 + sq * 4];
        pvb[u] = *(const uint4*)&Bpass[0][(size_t)row * 64 + 16 + sq * 4];
    }
    __syncthreads();

#pragma unroll 1
    for (int ch = 0; ch < 8; ch++) {
        const int buf = ch & 1;
        if (ch < 7) {
#pragma unroll
            for (int u = 0; u < 2; u++) {
                int row = srow + u * 64;
                *(uint4*)&As[buf ^ 1][row * PSTR + sq * 4] = pva[u];
                *(uint4*)&Bs[buf ^ 1][row * PSTR + sq * 4] = pvb[u];
            }
        }
        if (ch < 6) {
            int nc = ch + 2;
            const uint32_t* A_ = Apass[nc >> 2];
            const uint32_t* B_ = Bpass[nc >> 2];
            int koff = (nc & 3) * 16;
#pragma unroll
            for (int u = 0; u < 2; u++) {
                int row = srow + u * 64;
                pva[u] = *(const uint4*)&A_[(size_t)row * 64 + koff + sq * 4];
                pvb[u] = *(const uint4*)&B_[(size_t)row * 64 + koff + sq * 4];
            }
        }
#pragma unroll
        for (int ks = 0; ks < 2; ks++) {
            uint32_t a[2][4], b[8][2];
#pragma unroll
            for (int mi = 0; mi < 2; mi++) {
                int base = (wm * 32 + mi * 16 + g) * PSTR + ks * 8 + t;
                a[mi][0] = As[buf][base];
                a[mi][1] = As[buf][base + 8 * PSTR];
                a[mi][2] = As[buf][base + 4];
                a[mi][3] = As[buf][base + 8 * PSTR + 4];
            }
#pragma unroll
            for (int ni = 0; ni < 8; ni++) {
                int nb = (wn * 64 + ni * 8 + g) * PSTR + ks * 8 + t;
                b[ni][0] = Bs[buf][nb];
                b[ni][1] = Bs[buf][nb + 4];
            }
#pragma unroll
            for (int mi = 0; mi < 2; mi++)
#pragma unroll
                for (int ni = 0; ni < 8; ni++)
                    mma_f16(acc[mi][ni], a[mi], b[ni][0], b[ni][1]);
        }
        __syncthreads();
    }

    // ---- epilogue: bias + relu + layernorm + mask -> fp16 ----
    float cb[16], cgv[16], cbv[16];
#pragma unroll
    for (int ni = 0; ni < 8; ni++)
#pragma unroll
        for (int j = 0; j < 2; j++) {
            int c = wn * 64 + ni * 8 + 2 * t + j;
            cb[ni * 2 + j]  = bsb[c] + bnb[c];
            cgv[ni * 2 + j] = lng[c];
            cbv[ni * 2 + j] = lnb[c];
        }
#pragma unroll
    for (int mi = 0; mi < 2; mi++)
#pragma unroll
        for (int h = 0; h < 2; h++) {
            float s1 = 0.f, s2 = 0.f;
#pragma unroll
            for (int ni = 0; ni < 8; ni++)
#pragma unroll
                for (int j = 0; j < 2; j++) {
                    float v = fmaxf(acc[mi][ni][2 * h + j] + cb[ni * 2 + j], 0.f);
                    acc[mi][ni][2 * h + j] = v;
                    s1 += v;
                    s2 += v * v;
                }
            s1 += __shfl_xor_sync(0xffffffffu, s1, 1);
            s1 += __shfl_xor_sync(0xffffffffu, s1, 2);
            s2 += __shfl_xor_sync(0xffffffffu, s2, 1);
            s2 += __shfl_xor_sync(0xffffffffu, s2, 2);
            if (t == 0) {
                int row = wm * 32 + mi * 16 + g + 8 * h;
                red[row][wn * 2]     = s1;
                red[row][wn * 2 + 1] = s2;
            }
        }
    __syncthreads();
    uint32_t* xo32 = (uint32_t*)xout;
#pragma unroll
    for (int mi = 0; mi < 2; mi++)
#pragma unroll
        for (int h = 0; h < 2; h++) {
            int row = wm * 32 + mi * 16 + g + 8 * h;
            float s1 = red[row][0] + red[row][2];
            float s2 = red[row][1] + red[row][3];
            float mean = s1 * (1.0f / 128.0f);
            float var = fmaxf(s2 * (1.0f / 128.0f) - mean * mean, 0.f);
            float inv = rsqrtf(var + 1e-5f);
            int grow = m0 + row;
            float mk = nmask[grow];
#pragma unroll
            for (int ni = 0; ni < 8; ni++) {
                float ox = ((acc[mi][ni][2 * h]     - mean) * inv * cgv[ni * 2]     + cbv[ni * 2])     * mk;
                float oy = ((acc[mi][ni][2 * h + 1] - mean) * inv * cgv[ni * 2 + 1] + cbv[ni * 2 + 1]) * mk;
                xo32[(size_t)grow * 64 + wn * 32 + ni * 4 + t] = pkh2(ox, oy);
            }
        }
}

// ---------------- pool partial: coalesced uint2 reads ----------------
__global__ void pool_partial_kernel(const __half* __restrict__ x, const float* __restrict__ nmask,
                                    float* __restrict__ pp, float* __restrict__ pm) {
    int blk = blockIdx.x;
    int b = blk >> 5, nc = blk & 31;
    int t = threadIdx.x;
    int g = t >> 5, l = t & 31;
    const uint2* xv = (const uint2*)x;
    float s0 = 0.f, s1 = 0.f, s2 = 0.f, s3 = 0.f;
    float m0 = -INFINITY, m1 = -INFINITY, m2 = -INFINITY, m3 = -INFINITY;
#pragma unroll 4
    for (int i = 0; i < 32; i++) {
        int n = nc * 256 + g * 32 + i;
        float mk = nmask[b * NN + n];
        uint2 u = xv[((size_t)(b * NN + n)) * 32 + l];
        float2 p = uph2(u.x), q = uph2(u.y);
        s0 += p.x * mk; s1 += p.y * mk; s2 += q.x * mk; s3 += q.y * mk;
        if (mk > 0.f) {
            m0 = fmaxf(m0, p.x * mk); m1 = fmaxf(m1, p.y * mk);
            m2 = fmaxf(m2, q.x * mk); m3 = fmaxf(m3, q.y * mk);
        }
    }
    __shared__ float sh[8][32][4];
    sh[g][l][0] = s0; sh[g][l][1] = s1; sh[g][l][2] = s2; sh[g][l][3] = s3;
    __syncthreads();
    if (g < 4) {
        int c = g * 32 + l;
        int ll = c >> 2, j = c & 3;
        float acc = 0.f;
#pragma unroll
        for (int k = 0; k < 8; k++) acc += sh[k][ll][j];
        pp[blk * 128 + c] = acc;
    }
    __syncthreads();
    sh[g][l][0] = m0; sh[g][l][1] = m1; sh[g][l][2] = m2; sh[g][l][3] = m3;
    __syncthreads();
    if (g < 4) {
        int c = g * 32 + l;
        int ll = c >> 2, j = c & 3;
        float acc = -INFINITY;
#pragma unroll
        for (int k = 0; k < 8; k++) acc = fmaxf(acc, sh[k][ll][j]);
        pm[blk * 128 + c] = acc;
    }
}

// ---------------- fused pool-final + MLP ----------------
__global__ void mlp_kernel(const float* __restrict__ pp, const float* __restrict__ pm,
                           const float* __restrict__ nmask,
                           const float* __restrict__ W1, const float* __restrict__ b1,
                           const float* __restrict__ W2, const float* __restrict__ b2,
                           float* __restrict__ out) {
    __shared__ float gs[256], hs[128], sc[256];
    int b = blockIdx.x, tid = threadIdx.x;

    float cv = 0.f;
    for (int n = tid; n < NN; n += 256) cv += nmask[b * NN + n];
    sc[tid] = cv;
    __syncthreads();
    for (int d = 128; d; d >>= 1) {
        if (tid < d) sc[tid] += sc[tid + d];
        __syncthreads();
    }
    float cnt = fmaxf(sc[0], 1.f);

    {
        int c = tid & 127;
        if (tid < 128) {
            float s = 0.f;
#pragma unroll
            for (int k = 0; k < 32; k++) s += pp[(b * 32 + k) * 128 + c];
            gs[c] = s / cnt;
        } else {
            float mx = -INFINITY;
#pragma unroll
            for (int k = 0; k < 32; k++) mx = fmaxf(mx, pm[(b * 32 + k) * 128 + c]);
            gs[128 + c] = mx;
        }
    }
    __syncthreads();

    if (tid < 128) {
        float a = b1[tid];
        for (int k = 0; k < 256; k++) a = fmaf(gs[k], W1[k * 128 + tid], a);
        hs[tid] = fmaxf(a, 0.f);
    }
    __syncthreads();
    float a = b2[tid];
    for (int k = 0; k < 128; k++) a = fmaf(hs[k], W2[k * 256 + tid], a);
    out[b * 256 + tid] = a;
}

// ---------------- launch ----------------
extern "C" void kernel_launch(void* const* d_in, const int* in_sizes, int n_in,
                              void* d_out, int out_size) {
    const float* feats = (const float*)d_in[0];
    const int*   ei    = (const int*)d_in[1];
    const float* nmask = (const float*)d_in[2];
    const float* emask = (const float*)d_in[3];
    const float* inW   = (const float*)d_in[4];
    const float* inb   = (const float*)d_in[5];
    const float* sW    = (const float*)d_in[6];
    const float* sb    = (const float*)d_in[7];
    const float* nW    = (const float*)d_in[8];
    const float* nb    = (const float*)d_in[9];
    const float* lng   = (const float*)d_in[10];
    const float* lnb   = (const float*)d_in[11];
    const float* w1    = (const float*)d_in[12];
    const float* b1    = (const float*)d_in[13];
    const float* w2    = (const float*)d_in[14];
    const float* b2    = (const float*)d_in[15];

    __half *xh0, *xh1, *aggh;
    float *cw, *pp, *pm;
    uint32_t* wth;
    int *cnti, *off, *slot, *csrc;
    cudaGetSymbolAddress((void**)&xh0,  g_xh0);
    cudaGetSymbolAddress((void**)&xh1,  g_xh1);
    cudaGetSymbolAddress((void**)&aggh, g_aggh);
    cudaGetSymbolAddress((void**)&cnti, g_cnti);
    cudaGetSymbolAddress((void**)&off,  g_off);
    cudaGetSymbolAddress((void**)&slot, g_slot);
    cudaGetSymbolAddress((void**)&csrc, g_csrc);
    cudaGetSymbolAddress((void**)&cw,   g_cw);
    cudaGetSymbolAddress((void**)&wth,  g_wth);
    cudaGetSymbolAddress((void**)&pp,   g_pp);
    cudaGetSymbolAddress((void**)&pm,   g_pm);

    static cudaStream_t s1 = nullptr;
    static cudaEvent_t evFork = nullptr, evJoin = nullptr;
    if (s1 == nullptr) {
        cudaStreamCreateWithFlags(&s1, cudaStreamNonBlocking);
        cudaEventCreateWithFlags(&evFork, cudaEventDisableTiming);
        cudaEventCreateWithFlags(&evJoin, cudaEventDisableTiming);
    }

    // fork: side stream runs the input-projection chain
    cudaEventRecord(evFork, 0);
    cudaStreamWaitEvent(s1, evFork, 0);

    // main stream: CSR build chain
    cudaMemsetAsync(cnti, 0, MM * sizeof(int), 0);
    count_kernel<<<(ETOT + 255) / 256, 256>>>(ei, emask, cnti, slot);
    scan_kernel<<<64, 1024>>>(cnti, off);
    fill_kernel<<<(ETOT + 255) / 256, 256>>>(ei, emask, off, slot, csrc, cw);

    // side stream: weight pack + input GEMM
    wtrans_kernel<<<56, 256, 0, s1>>>(sW, nW, inW, wth);
    input_mma_kernel<<<MM / 128, 256, 0, s1>>>(feats, wth + WT6, inb, xh0);
    cudaEventRecord(evJoin, s1);
    cudaStreamWaitEvent(0, evJoin, 0);

    __half* xin = xh0;
    __half* xo  = xh1;
    for (int l = 0; l < 3; l++) {
        agg_csr_kernel<<<MM * 32 / 256, 256>>>(xin, off, csrc, cw, aggh);
        layer_mma_kernel<<<MM / 128, 256>>>(xin, aggh,
                                            wth + (size_t)(l * 2) * (HH * HH / 2),
                                            wth + (size_t)(l * 2 + 1) * (HH * HH / 2),
                                            sb + l * HH, nb + l * HH,
                                            lng + l * HH, lnb + l * HH,
                                            nmask, xo);
        __half* t = xin; xin = xo; xo = t;
    }

    pool_partial_kernel<<<256, 256>>>(xin, nmask, pp, pm);
    mlp_kernel<<<BB, 256>>>(pp, pm, nmask, w1, b1, w2, b2, (float*)d_out);
}